// round 4
// baseline (speedup 1.0000x reference)
#include <cuda_runtime.h>

#define NMAX 50000
#define EMAX 800000
#define D 128
#define H 8
#define ATT_SCALE 0.25f   // 1/sqrt(16)

// ---------------- scratch (device globals; no runtime allocation) ----------
__device__ __align__(16) float g_q[NMAX * D];
__device__ __align__(16) float g_k[NMAX * D];
__device__ __align__(16) float g_v[NMAX * D];
__device__ __align__(16) float g_s[NMAX * D];
__device__ __align__(16) float g_h[NMAX * D];     // inter-layer hidden
__device__ __align__(16) float g_msg[NMAX * D];   // unnormalized message accumulator
__device__ __align__(16) float g_alpha[(size_t)EMAX * H];
__device__ float g_m[NMAX * H];     // segment max
__device__ float g_den[NMAX * H];   // segment sum of exp
__device__ int   g_src[EMAX];
__device__ int   g_dst[EMAX];
__device__ int   g_is64;

// ---------------- edge_index dtype detection + conversion ------------------
// If edge_index is int64 (values < 2^31), every odd int32 word is zero.
// 256 samples -> P(misclassify int32 data) = (1/50000)^256 ~ 0.
__global__ void detect_kernel(const int* __restrict__ ei32)
{
    __shared__ int any_nonzero;
    if (threadIdx.x == 0) any_nonzero = 0;
    __syncthreads();
    int v = ei32[2 * threadIdx.x + 1];   // max index 511 < 1.6M, safe either way
    if (v != 0) any_nonzero = 1;         // benign race: all writers store 1
    __syncthreads();
    if (threadIdx.x == 0) g_is64 = any_nonzero ? 0 : 1;
}

__global__ void convert_kernel(const int* __restrict__ ei32, int E)
{
    int e = blockIdx.x * blockDim.x + threadIdx.x;
    if (e >= E) return;
    if (g_is64) {
        g_src[e] = ei32[2 * (size_t)e];
        g_dst[e] = ei32[2 * ((size_t)E + e)];
    } else {
        g_src[e] = ei32[e];
        g_dst[e] = ei32[(size_t)E + e];
    }
}

// ---------------- GEMM: Y = X @ W + b,  X:[N,128] W:[128,128] --------------
#define BM 64
#define BN 64
#define BK 32

__global__ void gemm_bias_kernel(const float* __restrict__ Xin,
                                 const float* __restrict__ W,
                                 const float* __restrict__ bias,
                                 int which,   // 0:q 1:k 2:v 3:s
                                 int N)
{
    const float* X = Xin ? Xin : g_h;
    float* Y = (which == 0) ? g_q : (which == 1) ? g_k : (which == 2) ? g_v : g_s;

    __shared__ float Xs[BM][BK + 1];
    __shared__ float Ws[BK][BN + 1];

    int bx = blockIdx.x;             // 0..1 (column tiles)
    int by = blockIdx.y;             // row tiles
    int tid = threadIdx.x;           // 256 threads
    int tx = tid & 15;
    int ty = tid >> 4;
    int row0 = by * BM;
    int col0 = bx * BN;

    float acc[4][4];
#pragma unroll
    for (int i = 0; i < 4; i++)
#pragma unroll
        for (int j = 0; j < 4; j++) acc[i][j] = 0.f;

    for (int kk = 0; kk < 128; kk += BK) {
        // load X tile: 64x32
#pragma unroll
        for (int i = 0; i < 8; i++) {
            int idx = tid + i * 256;
            int r = idx >> 5, c = idx & 31;
            int gr = row0 + r;
            Xs[r][c] = (gr < N) ? X[(size_t)gr * 128 + kk + c] : 0.f;
        }
        // load W tile: 32x64
#pragma unroll
        for (int i = 0; i < 8; i++) {
            int idx = tid + i * 256;
            int r = idx >> 6, c = idx & 63;
            Ws[r][c] = W[(size_t)(kk + r) * 128 + col0 + c];
        }
        __syncthreads();

#pragma unroll
        for (int k = 0; k < BK; k++) {
            float a[4], b[4];
#pragma unroll
            for (int i = 0; i < 4; i++) a[i] = Xs[ty * 4 + i][k];
#pragma unroll
            for (int j = 0; j < 4; j++) b[j] = Ws[k][tx * 4 + j];
#pragma unroll
            for (int i = 0; i < 4; i++)
#pragma unroll
                for (int j = 0; j < 4; j++) acc[i][j] += a[i] * b[j];
        }
        __syncthreads();
    }

#pragma unroll
    for (int i = 0; i < 4; i++) {
        int r = row0 + ty * 4 + i;
        if (r < N) {
#pragma unroll
            for (int j = 0; j < 4; j++) {
                int c = col0 + tx * 4 + j;
                Y[(size_t)r * 128 + c] = acc[i][j] + bias[c];
            }
        }
    }
}

// ---------------- init m/den/msg -------------------------------------------
__global__ void init_kernel(int N)
{
    int i = blockIdx.x * blockDim.x + threadIdx.x;
    if (i < N * H) {
        g_m[i] = __int_as_float(0xff800000);  // -inf
        g_den[i] = 0.f;
    }
    if (i < N * D) g_msg[i] = 0.f;
}

// ---------------- pass B: alpha + segment max -------------------------------
__device__ __forceinline__ void atomicMaxFloat(float* addr, float val)
{
    if (val >= 0.f) atomicMax((int*)addr, __float_as_int(val));
    else            atomicMin((unsigned int*)addr, __float_as_uint(val));
}

__global__ void edge_alpha_kernel(int E)
{
    int e = (int)((blockIdx.x * (unsigned)blockDim.x + threadIdx.x) >> 5);
    int lane = threadIdx.x & 31;
    if (e >= E) return;
    int s = g_src[e];
    int d = g_dst[e];

    float4 qv = __ldg((const float4*)(g_q + (size_t)d * D) + lane);
    float4 kv = __ldg((const float4*)(g_k + (size_t)s * D) + lane);
    float p = qv.x * kv.x + qv.y * kv.y + qv.z * kv.z + qv.w * kv.w;
    p += __shfl_xor_sync(0xffffffffu, p, 1);
    p += __shfl_xor_sync(0xffffffffu, p, 2);

    if ((lane & 3) == 0) {
        int h = lane >> 2;
        float a = p * ATT_SCALE;
        g_alpha[(size_t)e * H + h] = a;
        atomicMaxFloat(&g_m[(size_t)d * H + h], a);
    }
}

// ---------------- pass C: exp, denom, scatter message -----------------------
__global__ void edge_message_kernel(int E)
{
    int e = (int)((blockIdx.x * (unsigned)blockDim.x + threadIdx.x) >> 5);
    int lane = threadIdx.x & 31;
    if (e >= E) return;
    int s = g_src[e];
    int d = g_dst[e];
    int h = lane >> 2;

    float a = __expf(g_alpha[(size_t)e * H + h] - __ldg(&g_m[(size_t)d * H + h]));
    if ((lane & 3) == 0) atomicAdd(&g_den[(size_t)d * H + h], a);

    float4 vv = __ldg((const float4*)(g_v + (size_t)s * D) + lane);
    float* mp = g_msg + (size_t)d * D + lane * 4;
    atomicAdd(mp + 0, a * vv.x);
    atomicAdd(mp + 1, a * vv.y);
    atomicAdd(mp + 2, a * vv.z);
    atomicAdd(mp + 3, a * vv.w);
}

// ---------------- finalize: out = skip + msg/denom (+relu) ------------------
__global__ void finalize_kernel(float* __restrict__ outp, int N, int do_relu)
{
    int idx = blockIdx.x * blockDim.x + threadIdx.x;
    if (idx >= N * D) return;
    int n = idx >> 7;          // /128
    int c = idx & 127;
    int h = c >> 4;
    float den = g_den[n * H + h];
    float mterm = (den > 0.f) ? g_msg[idx] / den : 0.f;
    float o = g_s[idx] + mterm;
    if (do_relu) o = fmaxf(o, 0.f);
    float* op = outp ? outp : g_h;
    op[idx] = o;
}

// ---------------- host ------------------------------------------------------
extern "C" void kernel_launch(void* const* d_in, const int* in_sizes, int n_in,
                              void* d_out, int out_size)
{
    const float* x = (const float*)d_in[0];
    const int* ei32 = (const int*)d_in[1];   // int32 view; dtype detected on device
    int N = in_sizes[0] / 128;
    int E = in_sizes[1] / 2;

    const float* W[2][4] = {
        {(const float*)d_in[3], (const float*)d_in[5], (const float*)d_in[7], (const float*)d_in[9]},
        {(const float*)d_in[11], (const float*)d_in[13], (const float*)d_in[15], (const float*)d_in[17]}
    };
    const float* B[2][4] = {
        {(const float*)d_in[4], (const float*)d_in[6], (const float*)d_in[8], (const float*)d_in[10]},
        {(const float*)d_in[12], (const float*)d_in[14], (const float*)d_in[16], (const float*)d_in[18]}
    };

    detect_kernel<<<1, 256>>>(ei32);
    convert_kernel<<<(E + 255) / 256, 256>>>(ei32, E);

    dim3 ggrid(128 / BN, (N + BM - 1) / BM);
    int nd_blocks = (N * D + 255) / 256;
    int edge_blocks = (E + 7) / 8;   // 8 edges (warps) per 256-thread block

    for (int layer = 0; layer < 2; layer++) {
        const float* xin = (layer == 0) ? x : nullptr;   // nullptr -> g_h
        for (int w = 0; w < 4; w++)
            gemm_bias_kernel<<<ggrid, 256>>>(xin, W[layer][w], B[layer][w], w, N);
        init_kernel<<<nd_blocks, 256>>>(N);
        edge_alpha_kernel<<<edge_blocks, 256>>>(E);
        edge_message_kernel<<<edge_blocks, 256>>>(E);
        finalize_kernel<<<nd_blocks, 256>>>(layer == 0 ? nullptr : (float*)d_out, N,
                                            layer == 0 ? 1 : 0);
    }
}

// round 5
// speedup vs baseline: 2.3209x; 2.3209x over previous
#include <cuda_runtime.h>

#define NMAX 50000
#define EMAX 800000
#define D 128
#define H 8
#define ATT_SCALE 0.25f   // 1/sqrt(16)
#define NEG_INF __int_as_float(0xff800000)

// ---------------- scratch (device globals; no runtime allocation) ----------
__device__ __align__(16) float g_q[NMAX * D];
__device__ __align__(16) float g_k[NMAX * D];
__device__ __align__(16) float g_v[NMAX * D];
__device__ __align__(16) float g_s[NMAX * D];
__device__ __align__(16) float g_h[NMAX * D];     // inter-layer hidden
__device__ int   g_src[EMAX];
__device__ int   g_dst[EMAX];
__device__ int   g_rowptr[NMAX + 1];
__device__ int   g_cursor[NMAX + 1];
__device__ int   g_csrc[EMAX];                    // CSR: src node per incoming edge
__device__ int   g_blocksums[64];
__device__ int   g_is64;

// ---------------- edge_index dtype detection + conversion ------------------
__global__ void detect_kernel(const int* __restrict__ ei32)
{
    __shared__ int any_nonzero;
    if (threadIdx.x == 0) any_nonzero = 0;
    __syncthreads();
    int v = ei32[2 * threadIdx.x + 1];
    if (v != 0) any_nonzero = 1;
    __syncthreads();
    if (threadIdx.x == 0) g_is64 = any_nonzero ? 0 : 1;
}

__global__ void convert_kernel(const int* __restrict__ ei32, int E)
{
    int e = blockIdx.x * blockDim.x + threadIdx.x;
    if (e >= E) return;
    if (g_is64) {
        g_src[e] = ei32[2 * (size_t)e];
        g_dst[e] = ei32[2 * ((size_t)E + e)];
    } else {
        g_src[e] = ei32[e];
        g_dst[e] = ei32[(size_t)E + e];
    }
}

// ---------------- CSR build -------------------------------------------------
__global__ void zero_cnt_kernel(int N)
{
    int i = blockIdx.x * blockDim.x + threadIdx.x;
    if (i <= N) g_rowptr[i] = 0;
}

__global__ void hist_kernel(int E)
{
    int e = blockIdx.x * blockDim.x + threadIdx.x;
    if (e < E) atomicAdd(&g_rowptr[g_dst[e]], 1);
}

// block-level exclusive scan: 1024 elements per block (in place on g_rowptr)
__global__ void scan1_kernel(int Ntot)
{
    __shared__ int sh[1024];
    int t = threadIdx.x;
    int i = blockIdx.x * 1024 + t;
    int v = (i < Ntot) ? g_rowptr[i] : 0;
    sh[t] = v;
    for (int off = 1; off < 1024; off <<= 1) {
        __syncthreads();
        int x = (t >= off) ? sh[t - off] : 0;
        __syncthreads();
        sh[t] += x;
    }
    __syncthreads();
    if (i < Ntot) g_rowptr[i] = sh[t] - v;      // exclusive
    if (t == 1023) g_blocksums[blockIdx.x] = sh[t];
}

__global__ void scan2_kernel(int nb)
{
    if (threadIdx.x == 0) {
        int acc = 0;
        for (int b = 0; b < nb; b++) {
            int x = g_blocksums[b];
            g_blocksums[b] = acc;
            acc += x;
        }
    }
}

__global__ void scan3_kernel(int Ntot)
{
    int i = blockIdx.x * 1024 + threadIdx.x;
    if (i < Ntot) {
        int r = g_rowptr[i] + g_blocksums[blockIdx.x];
        g_rowptr[i] = r;
        g_cursor[i] = r;
    }
}

__global__ void scatter_kernel(int E)
{
    int e = blockIdx.x * blockDim.x + threadIdx.x;
    if (e >= E) return;
    int pos = atomicAdd(&g_cursor[g_dst[e]], 1);
    g_csrc[pos] = g_src[e];
}

// ---------------- fused GEMM: {q,k,v,s} = X @ W_i + b_i --------------------
// grid = (4, ceil(N/128)); block = 256; 128x128 tile, BK=16, 8x8 per thread
#define GBK 16

__global__ __launch_bounds__(256) void gemm4_kernel(
    const float* __restrict__ Xin,
    const float* __restrict__ Wq, const float* __restrict__ Wk,
    const float* __restrict__ Wv, const float* __restrict__ Ws_,
    const float* __restrict__ bq, const float* __restrict__ bk,
    const float* __restrict__ bv, const float* __restrict__ bs,
    int N)
{
    const float* X = Xin ? Xin : g_h;
    int which = blockIdx.x;
    const float* W = (which == 0) ? Wq : (which == 1) ? Wk : (which == 2) ? Wv : Ws_;
    const float* bias = (which == 0) ? bq : (which == 1) ? bk : (which == 2) ? bv : bs;
    float* Y = (which == 0) ? g_q : (which == 1) ? g_k : (which == 2) ? g_v : g_s;

    __shared__ float XsT[GBK][132];   // k-major, padded (float4-aligned rows)
    __shared__ float Wsh[GBK][128];

    int tid = threadIdx.x;
    int tx = tid & 15;
    int ty = tid >> 4;
    int row0 = blockIdx.y * 128;
    int r0 = ty * 8;
    int c0 = tx * 8;

    float acc[8][8];
#pragma unroll
    for (int i = 0; i < 8; i++)
#pragma unroll
        for (int j = 0; j < 8; j++) acc[i][j] = 0.f;

    for (int kk = 0; kk < 128; kk += GBK) {
        // load X tile [128 rows x 16 k] -> XsT[k][row]
#pragma unroll
        for (int l = 0; l < 2; l++) {
            int f = tid * 2 + l;            // 0..511 float4s
            int row = f >> 2;
            int cc = (f & 3) * 4;
            int gr = row0 + row;
            float4 xv = (gr < N) ? *(const float4*)(X + (size_t)gr * 128 + kk + cc)
                                 : make_float4(0.f, 0.f, 0.f, 0.f);
            XsT[cc + 0][row] = xv.x;
            XsT[cc + 1][row] = xv.y;
            XsT[cc + 2][row] = xv.z;
            XsT[cc + 3][row] = xv.w;
        }
        // load W tile [16 k x 128 cols]
#pragma unroll
        for (int l = 0; l < 2; l++) {
            int f = tid * 2 + l;
            int r = f >> 5;
            int cc = (f & 31) * 4;
            *(float4*)&Wsh[r][cc] = *(const float4*)(W + (size_t)(kk + r) * 128 + cc);
        }
        __syncthreads();

#pragma unroll
        for (int k = 0; k < GBK; k++) {
            float4 a0 = *(const float4*)&XsT[k][r0];
            float4 a1 = *(const float4*)&XsT[k][r0 + 4];
            float4 b0 = *(const float4*)&Wsh[k][c0];
            float4 b1 = *(const float4*)&Wsh[k][c0 + 4];
            float a[8] = {a0.x, a0.y, a0.z, a0.w, a1.x, a1.y, a1.z, a1.w};
            float b[8] = {b0.x, b0.y, b0.z, b0.w, b1.x, b1.y, b1.z, b1.w};
#pragma unroll
            for (int i = 0; i < 8; i++)
#pragma unroll
                for (int j = 0; j < 8; j++) acc[i][j] += a[i] * b[j];
        }
        __syncthreads();
    }

    float bb[8];
#pragma unroll
    for (int j = 0; j < 8; j++) bb[j] = bias[c0 + j];

#pragma unroll
    for (int i = 0; i < 8; i++) {
        int r = row0 + r0 + i;
        if (r < N) {
            float4 o0 = make_float4(acc[i][0] + bb[0], acc[i][1] + bb[1],
                                    acc[i][2] + bb[2], acc[i][3] + bb[3]);
            float4 o1 = make_float4(acc[i][4] + bb[4], acc[i][5] + bb[5],
                                    acc[i][6] + bb[6], acc[i][7] + bb[7]);
            *(float4*)(Y + (size_t)r * 128 + c0) = o0;
            *(float4*)(Y + (size_t)r * 128 + c0 + 4) = o1;
        }
    }
}

// ---------------- fused attention: gather + online softmax + skip ----------
// one warp per dst node; lane holds 4 channels (head = lane>>2)
__global__ void attn_gather_kernel(float* __restrict__ outp, int N, int do_relu)
{
    int wg = blockIdx.x * 8 + (threadIdx.x >> 5);
    if (wg >= N) return;
    int lane = threadIdx.x & 31;
    size_t off = (size_t)wg * D;

    float4 qv = *((const float4*)(g_q + off) + lane);

    int beg = g_rowptr[wg];
    int end = g_rowptr[wg + 1];

    float m = NEG_INF;
    float den = 0.f;
    float4 acc = make_float4(0.f, 0.f, 0.f, 0.f);

    for (int i = beg; i < end; i++) {
        int s = g_csrc[i];
        float4 kv = __ldg((const float4*)(g_k + (size_t)s * D) + lane);
        float4 vv = __ldg((const float4*)(g_v + (size_t)s * D) + lane);
        float p = qv.x * kv.x + qv.y * kv.y + qv.z * kv.z + qv.w * kv.w;
        p += __shfl_xor_sync(0xffffffffu, p, 1);
        p += __shfl_xor_sync(0xffffffffu, p, 2);
        float alpha = p * ATT_SCALE;
        float newm = fmaxf(m, alpha);
        float c = __expf(m - newm);       // first iter: exp(-inf)=0
        float w = __expf(alpha - newm);
        den = den * c + w;
        acc.x = acc.x * c + w * vv.x;
        acc.y = acc.y * c + w * vv.y;
        acc.z = acc.z * c + w * vv.z;
        acc.w = acc.w * c + w * vv.w;
        m = newm;
    }

    float4 sv = *((const float4*)(g_s + off) + lane);
    float inv = (den > 0.f) ? 1.f / den : 0.f;
    float4 o = make_float4(sv.x + acc.x * inv, sv.y + acc.y * inv,
                           sv.z + acc.z * inv, sv.w + acc.w * inv);
    if (do_relu) {
        o.x = fmaxf(o.x, 0.f); o.y = fmaxf(o.y, 0.f);
        o.z = fmaxf(o.z, 0.f); o.w = fmaxf(o.w, 0.f);
    }
    float* op = outp ? outp : g_h;
    *((float4*)(op + off) + lane) = o;
}

// ---------------- host ------------------------------------------------------
extern "C" void kernel_launch(void* const* d_in, const int* in_sizes, int n_in,
                              void* d_out, int out_size)
{
    const float* x = (const float*)d_in[0];
    const int* ei32 = (const int*)d_in[1];
    int N = in_sizes[0] / 128;
    int E = in_sizes[1] / 2;

    const float* W[2][4] = {
        {(const float*)d_in[3], (const float*)d_in[5], (const float*)d_in[7], (const float*)d_in[9]},
        {(const float*)d_in[11], (const float*)d_in[13], (const float*)d_in[15], (const float*)d_in[17]}
    };
    const float* B[2][4] = {
        {(const float*)d_in[4], (const float*)d_in[6], (const float*)d_in[8], (const float*)d_in[10]},
        {(const float*)d_in[12], (const float*)d_in[14], (const float*)d_in[16], (const float*)d_in[18]}
    };

    // edge decode + CSR build (per launch; deterministic work)
    detect_kernel<<<1, 256>>>(ei32);
    convert_kernel<<<(E + 255) / 256, 256>>>(ei32, E);
    int Ntot = N + 1;
    int nscan = (Ntot + 1023) / 1024;
    zero_cnt_kernel<<<(Ntot + 255) / 256, 256>>>(N);
    hist_kernel<<<(E + 255) / 256, 256>>>(E);
    scan1_kernel<<<nscan, 1024>>>(Ntot);
    scan2_kernel<<<1, 32>>>(nscan);
    scan3_kernel<<<nscan, 1024>>>(Ntot);
    scatter_kernel<<<(E + 255) / 256, 256>>>(E);

    dim3 ggrid(4, (N + 127) / 128);
    int attn_blocks = (N + 7) / 8;

    for (int layer = 0; layer < 2; layer++) {
        const float* xin = (layer == 0) ? x : nullptr;   // nullptr -> g_h
        gemm4_kernel<<<ggrid, 256>>>(xin,
            W[layer][0], W[layer][1], W[layer][2], W[layer][3],
            B[layer][0], B[layer][1], B[layer][2], B[layer][3], N);
        attn_gather_kernel<<<attn_blocks, 256>>>(
            layer == 0 ? nullptr : (float*)d_out, N, layer == 0 ? 1 : 0);
    }
}

// round 6
// speedup vs baseline: 2.9084x; 1.2532x over previous
#include <cuda_runtime.h>
#include <cstdint>

#define NMAX 50000
#define EMAX 800000
#define D 128
#define H 8
#define ATT_SCALE 0.25f   // 1/sqrt(16)
#define NEG_INF __int_as_float(0xff800000)

// ---------------- scratch (device globals; no runtime allocation) ----------
__device__ __align__(16) float g_q[NMAX * D];
__device__ __align__(16) float g_k[NMAX * D];
__device__ __align__(16) float g_v[NMAX * D];
__device__ __align__(16) float g_s[NMAX * D];
__device__ __align__(16) float g_h[NMAX * D];     // inter-layer hidden
__device__ int   g_src[EMAX];
__device__ int   g_dst[EMAX];
__device__ int   g_rowptr[NMAX + 1];
__device__ int   g_cursor[NMAX + 1];
__device__ int   g_csrc[EMAX];                    // CSR: src node per incoming edge
__device__ int   g_blocksums[64];
__device__ int   g_is64;

// ---------------- edge_index dtype detection ------------------------------
__global__ void detect_kernel(const int* __restrict__ ei32)
{
    __shared__ int any_nonzero;
    if (threadIdx.x == 0) any_nonzero = 0;
    __syncthreads();
    int v = ei32[2 * threadIdx.x + 1];
    if (v != 0) any_nonzero = 1;
    __syncthreads();
    if (threadIdx.x == 0) g_is64 = any_nonzero ? 0 : 1;
}

__global__ void zero_cnt_kernel(int N)
{
    int i = blockIdx.x * blockDim.x + threadIdx.x;
    if (i <= N) g_rowptr[i] = 0;
}

// fused convert + histogram
__global__ void convert_hist_kernel(const int* __restrict__ ei32, int E)
{
    int e = blockIdx.x * blockDim.x + threadIdx.x;
    if (e >= E) return;
    int s, d;
    if (g_is64) {
        s = ei32[2 * (size_t)e];
        d = ei32[2 * ((size_t)E + e)];
    } else {
        s = ei32[e];
        d = ei32[(size_t)E + e];
    }
    g_src[e] = s;
    g_dst[e] = d;
    atomicAdd(&g_rowptr[d], 1);
}

// block-level exclusive scan: 1024 elements per block (in place on g_rowptr)
__global__ void scan1_kernel(int Ntot)
{
    __shared__ int sh[1024];
    int t = threadIdx.x;
    int i = blockIdx.x * 1024 + t;
    int v = (i < Ntot) ? g_rowptr[i] : 0;
    sh[t] = v;
    for (int off = 1; off < 1024; off <<= 1) {
        __syncthreads();
        int x = (t >= off) ? sh[t - off] : 0;
        __syncthreads();
        sh[t] += x;
    }
    __syncthreads();
    if (i < Ntot) g_rowptr[i] = sh[t] - v;      // exclusive
    if (t == 1023) g_blocksums[blockIdx.x] = sh[t];
}

__global__ void scan2_kernel(int nb)
{
    if (threadIdx.x == 0) {
        int acc = 0;
        for (int b = 0; b < nb; b++) {
            int x = g_blocksums[b];
            g_blocksums[b] = acc;
            acc += x;
        }
    }
}

__global__ void scan3_kernel(int Ntot)
{
    int i = blockIdx.x * 1024 + threadIdx.x;
    if (i < Ntot) {
        int r = g_rowptr[i] + g_blocksums[blockIdx.x];
        g_rowptr[i] = r;
        g_cursor[i] = r;
    }
}

__global__ void scatter_kernel(int E)
{
    int e = blockIdx.x * blockDim.x + threadIdx.x;
    if (e >= E) return;
    int pos = atomicAdd(&g_cursor[g_dst[e]], 1);
    g_csrc[pos] = g_src[e];
}

// ---------------- tf32 split helpers ----------------------------------------
__device__ __forceinline__ void split_tf32(float x, float& hi, float& lo)
{
    asm("cvt.rna.tf32.f32 %0, %1;" : "=f"(hi) : "f"(x));
    float r = x - hi;
    asm("cvt.rna.tf32.f32 %0, %1;" : "=f"(lo) : "f"(r));
}

__device__ __forceinline__ void mma_tf32(float* c, const uint32_t* a,
                                         uint32_t b0, uint32_t b1)
{
    asm volatile(
        "mma.sync.aligned.m16n8k8.row.col.f32.tf32.tf32.f32 "
        "{%0,%1,%2,%3}, {%4,%5,%6,%7}, {%8,%9}, {%0,%1,%2,%3};"
        : "+f"(c[0]), "+f"(c[1]), "+f"(c[2]), "+f"(c[3])
        : "r"(a[0]), "r"(a[1]), "r"(a[2]), "r"(a[3]), "r"(b0), "r"(b1));
}

// ---------------- fused GEMM: {q,k,v,s} = X @ W_i + b_i (tf32 tensor cores) -
// grid = (4, ceil(N/128)); block = 256 (8 warps, 4x2); warp tile 32x64
// split-tf32: Y = Ah*Bh + Ah*Bl + Al*Bh  (fp32-accurate)
#define XS_PAD 20
#define WS_PAD 136

__global__ __launch_bounds__(256, 2) void gemm4_kernel(
    const float* __restrict__ Xin,
    const float* __restrict__ Wq, const float* __restrict__ Wk,
    const float* __restrict__ Wv, const float* __restrict__ Ws_,
    const float* __restrict__ bq, const float* __restrict__ bk,
    const float* __restrict__ bv, const float* __restrict__ bs,
    int N)
{
    const float* X = Xin ? Xin : g_h;
    int which = blockIdx.x;
    const float* W = (which == 0) ? Wq : (which == 1) ? Wk : (which == 2) ? Wv : Ws_;
    const float* bias = (which == 0) ? bq : (which == 1) ? bk : (which == 2) ? bv : bs;
    float* Y = (which == 0) ? g_q : (which == 1) ? g_k : (which == 2) ? g_v : g_s;

    __shared__ float Xh[128][XS_PAD];
    __shared__ float Xl[128][XS_PAD];
    __shared__ float Wh[16][WS_PAD];
    __shared__ float Wl[16][WS_PAD];

    int tid  = threadIdx.x;
    int lane = tid & 31;
    int warp = tid >> 5;
    int wm   = warp & 3;          // m offset = wm*32
    int wn   = warp >> 2;         // n offset = wn*64
    int lx   = lane & 3;
    int ly   = lane >> 2;
    int row0 = blockIdx.y * 128;

    float acc[2][8][4];
#pragma unroll
    for (int i = 0; i < 2; i++)
#pragma unroll
        for (int j = 0; j < 8; j++)
#pragma unroll
            for (int t = 0; t < 4; t++) acc[i][j][t] = 0.f;

    for (int kk = 0; kk < 128; kk += 16) {
        // load X tile [128 x 16] -> hi/lo splits
#pragma unroll
        for (int l = 0; l < 2; l++) {
            int f = tid + l * 256;          // 0..511
            int m = f >> 2;
            int c4 = (f & 3) * 4;
            int gr = row0 + m;
            float4 xv = (gr < N) ? *(const float4*)(X + (size_t)gr * 128 + kk + c4)
                                 : make_float4(0.f, 0.f, 0.f, 0.f);
            float h0, l0, h1, l1, h2, l2, h3, l3;
            split_tf32(xv.x, h0, l0); split_tf32(xv.y, h1, l1);
            split_tf32(xv.z, h2, l2); split_tf32(xv.w, h3, l3);
            *(float4*)&Xh[m][c4] = make_float4(h0, h1, h2, h3);
            *(float4*)&Xl[m][c4] = make_float4(l0, l1, l2, l3);
        }
        // load W tile [16 x 128] -> hi/lo splits
#pragma unroll
        for (int l = 0; l < 2; l++) {
            int f = tid + l * 256;
            int r = f >> 5;
            int c4 = (f & 31) * 4;
            float4 wv = *(const float4*)(W + (size_t)(kk + r) * 128 + c4);
            float h0, l0, h1, l1, h2, l2, h3, l3;
            split_tf32(wv.x, h0, l0); split_tf32(wv.y, h1, l1);
            split_tf32(wv.z, h2, l2); split_tf32(wv.w, h3, l3);
            *(float4*)&Wh[r][c4] = make_float4(h0, h1, h2, h3);
            *(float4*)&Wl[r][c4] = make_float4(l0, l1, l2, l3);
        }
        __syncthreads();

#pragma unroll
        for (int s = 0; s < 2; s++) {       // two k8 sub-steps
            uint32_t ah[2][4], al[2][4];
#pragma unroll
            for (int i = 0; i < 2; i++) {
                int r = wm * 32 + i * 16 + ly;
                int c = s * 8 + lx;
                ah[i][0] = __float_as_uint(Xh[r][c]);
                ah[i][1] = __float_as_uint(Xh[r + 8][c]);
                ah[i][2] = __float_as_uint(Xh[r][c + 4]);
                ah[i][3] = __float_as_uint(Xh[r + 8][c + 4]);
                al[i][0] = __float_as_uint(Xl[r][c]);
                al[i][1] = __float_as_uint(Xl[r + 8][c]);
                al[i][2] = __float_as_uint(Xl[r][c + 4]);
                al[i][3] = __float_as_uint(Xl[r + 8][c + 4]);
            }
#pragma unroll
            for (int j = 0; j < 8; j++) {
                int n = wn * 64 + j * 8 + ly;
                int kr = s * 8 + lx;
                uint32_t bh0 = __float_as_uint(Wh[kr][n]);
                uint32_t bh1 = __float_as_uint(Wh[kr + 4][n]);
                uint32_t bl0 = __float_as_uint(Wl[kr][n]);
                uint32_t bl1 = __float_as_uint(Wl[kr + 4][n]);
#pragma unroll
                for (int i = 0; i < 2; i++) {
                    mma_tf32(acc[i][j], ah[i], bh0, bh1);   // Ah*Bh
                    mma_tf32(acc[i][j], al[i], bh0, bh1);   // Al*Bh
                    mma_tf32(acc[i][j], ah[i], bl0, bl1);   // Ah*Bl
                }
            }
        }
        __syncthreads();
    }

    // epilogue: bias add + guarded store (c0,c1 at row; c2,c3 at row+8)
#pragma unroll
    for (int i = 0; i < 2; i++) {
        int rg = row0 + wm * 32 + i * 16 + ly;
#pragma unroll
        for (int j = 0; j < 8; j++) {
            int cg = wn * 64 + j * 8 + 2 * lx;
            float2 bb = *(const float2*)(bias + cg);
            if (rg < N) {
                float2 o = make_float2(acc[i][j][0] + bb.x, acc[i][j][1] + bb.y);
                *(float2*)(Y + (size_t)rg * 128 + cg) = o;
            }
            if (rg + 8 < N) {
                float2 o = make_float2(acc[i][j][2] + bb.x, acc[i][j][3] + bb.y);
                *(float2*)(Y + (size_t)(rg + 8) * 128 + cg) = o;
            }
        }
    }
}

// ---------------- fused attention: gather + online softmax + skip ----------
// one warp per dst node; lane holds 4 channels (head = lane>>2)
__global__ void attn_gather_kernel(float* __restrict__ outp, int N, int do_relu)
{
    int wg = blockIdx.x * 8 + (threadIdx.x >> 5);
    if (wg >= N) return;
    int lane = threadIdx.x & 31;
    size_t off = (size_t)wg * D;

    float4 qv = *((const float4*)(g_q + off) + lane);

    int beg = g_rowptr[wg];
    int end = g_rowptr[wg + 1];

    float m = NEG_INF;
    float den = 0.f;
    float4 acc = make_float4(0.f, 0.f, 0.f, 0.f);

    int s_next = (beg < end) ? __ldg(&g_csrc[beg]) : 0;
    for (int i = beg; i < end; i++) {
        int s = s_next;
        if (i + 1 < end) s_next = __ldg(&g_csrc[i + 1]);
        float4 kv = __ldg((const float4*)(g_k + (size_t)s * D) + lane);
        float4 vv = __ldg((const float4*)(g_v + (size_t)s * D) + lane);
        float p = qv.x * kv.x + qv.y * kv.y + qv.z * kv.z + qv.w * kv.w;
        p += __shfl_xor_sync(0xffffffffu, p, 1);
        p += __shfl_xor_sync(0xffffffffu, p, 2);
        float alpha = p * ATT_SCALE;
        float newm = fmaxf(m, alpha);
        float c = __expf(m - newm);       // first iter: exp(-inf)=0
        float w = __expf(alpha - newm);
        den = den * c + w;
        acc.x = acc.x * c + w * vv.x;
        acc.y = acc.y * c + w * vv.y;
        acc.z = acc.z * c + w * vv.z;
        acc.w = acc.w * c + w * vv.w;
        m = newm;
    }

    float4 sv = *((const float4*)(g_s + off) + lane);
    float inv = (den > 0.f) ? 1.f / den : 0.f;
    float4 o = make_float4(sv.x + acc.x * inv, sv.y + acc.y * inv,
                           sv.z + acc.z * inv, sv.w + acc.w * inv);
    if (do_relu) {
        o.x = fmaxf(o.x, 0.f); o.y = fmaxf(o.y, 0.f);
        o.z = fmaxf(o.z, 0.f); o.w = fmaxf(o.w, 0.f);
    }
    float* op = outp ? outp : g_h;
    *((float4*)(op + off) + lane) = o;
}

// ---------------- host ------------------------------------------------------
extern "C" void kernel_launch(void* const* d_in, const int* in_sizes, int n_in,
                              void* d_out, int out_size)
{
    const float* x = (const float*)d_in[0];
    const int* ei32 = (const int*)d_in[1];
    int N = in_sizes[0] / 128;
    int E = in_sizes[1] / 2;

    const float* W[2][4] = {
        {(const float*)d_in[3], (const float*)d_in[5], (const float*)d_in[7], (const float*)d_in[9]},
        {(const float*)d_in[11], (const float*)d_in[13], (const float*)d_in[15], (const float*)d_in[17]}
    };
    const float* B[2][4] = {
        {(const float*)d_in[4], (const float*)d_in[6], (const float*)d_in[8], (const float*)d_in[10]},
        {(const float*)d_in[12], (const float*)d_in[14], (const float*)d_in[16], (const float*)d_in[18]}
    };

    // edge decode + CSR build (per launch; deterministic work)
    detect_kernel<<<1, 256>>>(ei32);
    int Ntot = N + 1;
    int nscan = (Ntot + 1023) / 1024;
    zero_cnt_kernel<<<(Ntot + 255) / 256, 256>>>(N);
    convert_hist_kernel<<<(E + 255) / 256, 256>>>(ei32, E);
    scan1_kernel<<<nscan, 1024>>>(Ntot);
    scan2_kernel<<<1, 32>>>(nscan);
    scan3_kernel<<<nscan, 1024>>>(Ntot);
    scatter_kernel<<<(E + 255) / 256, 256>>>(E);

    dim3 ggrid(4, (N + 127) / 128);
    int attn_blocks = (N + 7) / 8;

    for (int layer = 0; layer < 2; layer++) {
        const float* xin = (layer == 0) ? x : nullptr;   // nullptr -> g_h
        gemm4_kernel<<<ggrid, 256>>>(xin,
            W[layer][0], W[layer][1], W[layer][2], W[layer][3],
            B[layer][0], B[layer][1], B[layer][2], B[layer][3], N);
        attn_gather_kernel<<<attn_blocks, 256>>>(
            layer == 0 ? nullptr : (float*)d_out, N, layer == 0 ? 1 : 0);
    }
}

// round 7
// speedup vs baseline: 3.2454x; 1.1159x over previous
#include <cuda_runtime.h>
#include <cstdint>

#define NMAX 50000
#define EMAX 800000
#define D 128
#define H 8
#define ATT_SCALE 0.25f   // 1/sqrt(16)
#define NEG_INF __int_as_float(0xff800000)

// ---------------- scratch (device globals; no runtime allocation) ----------
__device__ __align__(16) float g_q[NMAX * D];
__device__ __align__(16) float g_k[NMAX * D];
__device__ __align__(16) float g_v[NMAX * D];
__device__ __align__(16) float g_s[NMAX * D];
__device__ __align__(16) float g_h[NMAX * D];     // inter-layer hidden
__device__ int   g_src[EMAX];
__device__ int   g_dst[EMAX];
__device__ int   g_rowptr[NMAX + 1];
__device__ int   g_cursor[NMAX + 1];
__device__ int   g_csrc[EMAX];                    // CSR: src node per incoming edge
__device__ int   g_blocksums[64];
__device__ int   g_is64;

// ---------------- edge_index dtype detection ------------------------------
__global__ void detect_kernel(const int* __restrict__ ei32)
{
    __shared__ int any_nonzero;
    if (threadIdx.x == 0) any_nonzero = 0;
    __syncthreads();
    int v = ei32[2 * threadIdx.x + 1];
    if (v != 0) any_nonzero = 1;
    __syncthreads();
    if (threadIdx.x == 0) g_is64 = any_nonzero ? 0 : 1;
}

__global__ void zero_cnt_kernel(int N)
{
    int i = blockIdx.x * blockDim.x + threadIdx.x;
    if (i <= N) g_rowptr[i] = 0;
}

// fused convert + histogram
__global__ void convert_hist_kernel(const int* __restrict__ ei32, int E)
{
    int e = blockIdx.x * blockDim.x + threadIdx.x;
    if (e >= E) return;
    int s, d;
    if (g_is64) {
        s = ei32[2 * (size_t)e];
        d = ei32[2 * ((size_t)E + e)];
    } else {
        s = ei32[e];
        d = ei32[(size_t)E + e];
    }
    g_src[e] = s;
    g_dst[e] = d;
    atomicAdd(&g_rowptr[d], 1);
}

// block-level exclusive scan: 1024 elements per block (in place on g_rowptr)
__global__ void scan1_kernel(int Ntot)
{
    __shared__ int sh[1024];
    int t = threadIdx.x;
    int i = blockIdx.x * 1024 + t;
    int v = (i < Ntot) ? g_rowptr[i] : 0;
    sh[t] = v;
    for (int off = 1; off < 1024; off <<= 1) {
        __syncthreads();
        int x = (t >= off) ? sh[t - off] : 0;
        __syncthreads();
        sh[t] += x;
    }
    __syncthreads();
    if (i < Ntot) g_rowptr[i] = sh[t] - v;      // exclusive
    if (t == 1023) g_blocksums[blockIdx.x] = sh[t];
}

__global__ void scan2_kernel(int nb)
{
    if (threadIdx.x == 0) {
        int acc = 0;
        for (int b = 0; b < nb; b++) {
            int x = g_blocksums[b];
            g_blocksums[b] = acc;
            acc += x;
        }
    }
}

__global__ void scan3_kernel(int Ntot)
{
    int i = blockIdx.x * 1024 + threadIdx.x;
    if (i < Ntot) {
        int r = g_rowptr[i] + g_blocksums[blockIdx.x];
        g_rowptr[i] = r;
        g_cursor[i] = r;
    }
}

__global__ void scatter_kernel(int E)
{
    int e = blockIdx.x * blockDim.x + threadIdx.x;
    if (e >= E) return;
    int pos = atomicAdd(&g_cursor[g_dst[e]], 1);
    g_csrc[pos] = g_src[e];
}

// ---------------- tf32 split helpers ----------------------------------------
__device__ __forceinline__ void split_tf32(float x, float& hi, float& lo)
{
    asm("cvt.rna.tf32.f32 %0, %1;" : "=f"(hi) : "f"(x));
    float r = x - hi;
    asm("cvt.rna.tf32.f32 %0, %1;" : "=f"(lo) : "f"(r));
}

__device__ __forceinline__ void mma_tf32(float* c, const uint32_t* a,
                                         uint32_t b0, uint32_t b1)
{
    asm volatile(
        "mma.sync.aligned.m16n8k8.row.col.f32.tf32.tf32.f32 "
        "{%0,%1,%2,%3}, {%4,%5,%6,%7}, {%8,%9}, {%0,%1,%2,%3};"
        : "+f"(c[0]), "+f"(c[1]), "+f"(c[2]), "+f"(c[3])
        : "r"(a[0]), "r"(a[1]), "r"(a[2]), "r"(a[3]), "r"(b0), "r"(b1));
}

// ---------------- fused GEMM: {q,k,v,s} = X @ W_i + b_i (tf32 tensor cores) -
// grid = (4, ceil(N/128)); block = 256 (8 warps, 4x2); warp tile 32x64
// split-tf32: Y = Ah*Bh + Ah*Bl + Al*Bh  (fp32-accurate)
// register-prefetch software pipeline over 8 k-steps of 16
#define XS_PAD 20
#define WS_PAD 136

__global__ __launch_bounds__(256, 2) void gemm4_kernel(
    const float* __restrict__ Xin,
    const float* __restrict__ Wq, const float* __restrict__ Wk,
    const float* __restrict__ Wv, const float* __restrict__ Ws_,
    const float* __restrict__ bq, const float* __restrict__ bk,
    const float* __restrict__ bv, const float* __restrict__ bs,
    int N)
{
    const float* X = Xin ? Xin : g_h;
    int which = blockIdx.x;
    const float* W = (which == 0) ? Wq : (which == 1) ? Wk : (which == 2) ? Wv : Ws_;
    const float* bias = (which == 0) ? bq : (which == 1) ? bk : (which == 2) ? bv : bs;
    float* Y = (which == 0) ? g_q : (which == 1) ? g_k : (which == 2) ? g_v : g_s;

    __shared__ float Xh[128][XS_PAD];
    __shared__ float Xl[128][XS_PAD];
    __shared__ float Wh[16][WS_PAD];
    __shared__ float Wl[16][WS_PAD];

    int tid  = threadIdx.x;
    int lane = tid & 31;
    int warp = tid >> 5;
    int wm   = warp & 3;          // m offset = wm*32
    int wn   = warp >> 2;         // n offset = wn*64
    int lx   = lane & 3;
    int ly   = lane >> 2;
    int row0 = blockIdx.y * 128;

    // per-thread load coordinates (X: 2 float4, W: 2 float4 per k-step)
    int xm[2], xc[2], wr[2], wc[2];
#pragma unroll
    for (int l = 0; l < 2; l++) {
        int f = tid + l * 256;
        xm[l] = f >> 2;
        xc[l] = (f & 3) * 4;
        wr[l] = f >> 5;
        wc[l] = (f & 31) * 4;
    }

    float acc[2][8][4];
#pragma unroll
    for (int i = 0; i < 2; i++)
#pragma unroll
        for (int j = 0; j < 8; j++)
#pragma unroll
            for (int t = 0; t < 4; t++) acc[i][j][t] = 0.f;

    // prefetch k-step 0
    float4 xv[2], wv[2];
#pragma unroll
    for (int l = 0; l < 2; l++) {
        int gr = row0 + xm[l];
        xv[l] = (gr < N) ? *(const float4*)(X + (size_t)gr * 128 + xc[l])
                         : make_float4(0.f, 0.f, 0.f, 0.f);
        wv[l] = *(const float4*)(W + (size_t)wr[l] * 128 + wc[l]);
    }

    for (int step = 0; step < 8; step++) {
        // split + store current tile
#pragma unroll
        for (int l = 0; l < 2; l++) {
            float h0, l0, h1, l1, h2, l2, h3, l3;
            split_tf32(xv[l].x, h0, l0); split_tf32(xv[l].y, h1, l1);
            split_tf32(xv[l].z, h2, l2); split_tf32(xv[l].w, h3, l3);
            *(float4*)&Xh[xm[l]][xc[l]] = make_float4(h0, h1, h2, h3);
            *(float4*)&Xl[xm[l]][xc[l]] = make_float4(l0, l1, l2, l3);
            split_tf32(wv[l].x, h0, l0); split_tf32(wv[l].y, h1, l1);
            split_tf32(wv[l].z, h2, l2); split_tf32(wv[l].w, h3, l3);
            *(float4*)&Wh[wr[l]][wc[l]] = make_float4(h0, h1, h2, h3);
            *(float4*)&Wl[wr[l]][wc[l]] = make_float4(l0, l1, l2, l3);
        }
        __syncthreads();

        // prefetch next tile into registers (overlaps with MMA below)
        if (step < 7) {
            int kk = (step + 1) * 16;
#pragma unroll
            for (int l = 0; l < 2; l++) {
                int gr = row0 + xm[l];
                xv[l] = (gr < N) ? *(const float4*)(X + (size_t)gr * 128 + kk + xc[l])
                                 : make_float4(0.f, 0.f, 0.f, 0.f);
                wv[l] = *(const float4*)(W + (size_t)(kk + wr[l]) * 128 + wc[l]);
            }
        }

#pragma unroll
        for (int s = 0; s < 2; s++) {       // two k8 sub-steps
            uint32_t ah[2][4], al[2][4];
#pragma unroll
            for (int i = 0; i < 2; i++) {
                int r = wm * 32 + i * 16 + ly;
                int c = s * 8 + lx;
                ah[i][0] = __float_as_uint(Xh[r][c]);
                ah[i][1] = __float_as_uint(Xh[r + 8][c]);
                ah[i][2] = __float_as_uint(Xh[r][c + 4]);
                ah[i][3] = __float_as_uint(Xh[r + 8][c + 4]);
                al[i][0] = __float_as_uint(Xl[r][c]);
                al[i][1] = __float_as_uint(Xl[r + 8][c]);
                al[i][2] = __float_as_uint(Xl[r][c + 4]);
                al[i][3] = __float_as_uint(Xl[r + 8][c + 4]);
            }
#pragma unroll
            for (int j = 0; j < 8; j++) {
                int n = wn * 64 + j * 8 + ly;
                int kr = s * 8 + lx;
                uint32_t bh0 = __float_as_uint(Wh[kr][n]);
                uint32_t bh1 = __float_as_uint(Wh[kr + 4][n]);
                uint32_t bl0 = __float_as_uint(Wl[kr][n]);
                uint32_t bl1 = __float_as_uint(Wl[kr + 4][n]);
#pragma unroll
                for (int i = 0; i < 2; i++) {
                    mma_tf32(acc[i][j], ah[i], bh0, bh1);   // Ah*Bh
                    mma_tf32(acc[i][j], al[i], bh0, bh1);   // Al*Bh
                    mma_tf32(acc[i][j], ah[i], bl0, bl1);   // Ah*Bl
                }
            }
        }
        __syncthreads();
    }

    // epilogue: bias add + guarded store (c0,c1 at row; c2,c3 at row+8)
#pragma unroll
    for (int i = 0; i < 2; i++) {
        int rg = row0 + wm * 32 + i * 16 + ly;
#pragma unroll
        for (int j = 0; j < 8; j++) {
            int cg = wn * 64 + j * 8 + 2 * lx;
            float2 bb = *(const float2*)(bias + cg);
            if (rg < N) {
                float2 o = make_float2(acc[i][j][0] + bb.x, acc[i][j][1] + bb.y);
                *(float2*)(Y + (size_t)rg * 128 + cg) = o;
            }
            if (rg + 8 < N) {
                float2 o = make_float2(acc[i][j][2] + bb.x, acc[i][j][3] + bb.y);
                *(float2*)(Y + (size_t)(rg + 8) * 128 + cg) = o;
            }
        }
    }
}

// ---------------- fused attention: gather + online softmax + skip ----------
// one warp per dst node; lane holds 4 channels (head = lane>>2); edge loop x4
__device__ __forceinline__ float edge_dot(float4 qv, float4 kv)
{
    float p = qv.x * kv.x + qv.y * kv.y + qv.z * kv.z + qv.w * kv.w;
    p += __shfl_xor_sync(0xffffffffu, p, 1);
    p += __shfl_xor_sync(0xffffffffu, p, 2);
    return p * ATT_SCALE;
}

__global__ void attn_gather_kernel(float* __restrict__ outp, int N, int do_relu)
{
    int wg = blockIdx.x * 8 + (threadIdx.x >> 5);
    if (wg >= N) return;
    int lane = threadIdx.x & 31;
    size_t off = (size_t)wg * D;

    float4 qv = *((const float4*)(g_q + off) + lane);

    int beg = g_rowptr[wg];
    int end = g_rowptr[wg + 1];

    float m = NEG_INF;
    float den = 0.f;
    float4 acc = make_float4(0.f, 0.f, 0.f, 0.f);

    int i = beg;
    for (; i + 4 <= end; i += 4) {
        int s0 = __ldg(&g_csrc[i]);
        int s1 = __ldg(&g_csrc[i + 1]);
        int s2 = __ldg(&g_csrc[i + 2]);
        int s3 = __ldg(&g_csrc[i + 3]);
        float4 k0 = __ldg((const float4*)(g_k + (size_t)s0 * D) + lane);
        float4 k1 = __ldg((const float4*)(g_k + (size_t)s1 * D) + lane);
        float4 k2 = __ldg((const float4*)(g_k + (size_t)s2 * D) + lane);
        float4 k3 = __ldg((const float4*)(g_k + (size_t)s3 * D) + lane);
        float4 v0 = __ldg((const float4*)(g_v + (size_t)s0 * D) + lane);
        float4 v1 = __ldg((const float4*)(g_v + (size_t)s1 * D) + lane);
        float4 v2 = __ldg((const float4*)(g_v + (size_t)s2 * D) + lane);
        float4 v3 = __ldg((const float4*)(g_v + (size_t)s3 * D) + lane);

        float a0 = edge_dot(qv, k0);
        float a1 = edge_dot(qv, k1);
        float a2 = edge_dot(qv, k2);
        float a3 = edge_dot(qv, k3);

        float mx = fmaxf(fmaxf(a0, a1), fmaxf(a2, a3));
        float newm = fmaxf(m, mx);
        float c  = __expf(m - newm);        // first group: exp(-inf)=0
        float w0 = __expf(a0 - newm);
        float w1 = __expf(a1 - newm);
        float w2 = __expf(a2 - newm);
        float w3 = __expf(a3 - newm);
        den = den * c + (w0 + w1) + (w2 + w3);
        acc.x = acc.x * c + w0 * v0.x + w1 * v1.x + w2 * v2.x + w3 * v3.x;
        acc.y = acc.y * c + w0 * v0.y + w1 * v1.y + w2 * v2.y + w3 * v3.y;
        acc.z = acc.z * c + w0 * v0.z + w1 * v1.z + w2 * v2.z + w3 * v3.z;
        acc.w = acc.w * c + w0 * v0.w + w1 * v1.w + w2 * v2.w + w3 * v3.w;
        m = newm;
    }
    for (; i < end; i++) {
        int s = __ldg(&g_csrc[i]);
        float4 kv = __ldg((const float4*)(g_k + (size_t)s * D) + lane);
        float4 vv = __ldg((const float4*)(g_v + (size_t)s * D) + lane);
        float alpha = edge_dot(qv, kv);
        float newm = fmaxf(m, alpha);
        float c = __expf(m - newm);
        float w = __expf(alpha - newm);
        den = den * c + w;
        acc.x = acc.x * c + w * vv.x;
        acc.y = acc.y * c + w * vv.y;
        acc.z = acc.z * c + w * vv.z;
        acc.w = acc.w * c + w * vv.w;
        m = newm;
    }

    float4 sv = *((const float4*)(g_s + off) + lane);
    float inv = (den > 0.f) ? 1.f / den : 0.f;
    float4 o = make_float4(sv.x + acc.x * inv, sv.y + acc.y * inv,
                           sv.z + acc.z * inv, sv.w + acc.w * inv);
    if (do_relu) {
        o.x = fmaxf(o.x, 0.f); o.y = fmaxf(o.y, 0.f);
        o.z = fmaxf(o.z, 0.f); o.w = fmaxf(o.w, 0.f);
    }
    float* op = outp ? outp : g_h;
    *((float4*)(op + off) + lane) = o;
}

// ---------------- host ------------------------------------------------------
extern "C" void kernel_launch(void* const* d_in, const int* in_sizes, int n_in,
                              void* d_out, int out_size)
{
    const float* x = (const float*)d_in[0];
    const int* ei32 = (const int*)d_in[1];
    int N = in_sizes[0] / 128;
    int E = in_sizes[1] / 2;

    const float* W[2][4] = {
        {(const float*)d_in[3], (const float*)d_in[5], (const float*)d_in[7], (const float*)d_in[9]},
        {(const float*)d_in[11], (const float*)d_in[13], (const float*)d_in[15], (const float*)d_in[17]}
    };
    const float* B[2][4] = {
        {(const float*)d_in[4], (const float*)d_in[6], (const float*)d_in[8], (const float*)d_in[10]},
        {(const float*)d_in[12], (const float*)d_in[14], (const float*)d_in[16], (const float*)d_in[18]}
    };

    // edge decode + CSR build (per launch; deterministic work)
    detect_kernel<<<1, 256>>>(ei32);
    int Ntot = N + 1;
    int nscan = (Ntot + 1023) / 1024;
    zero_cnt_kernel<<<(Ntot + 255) / 256, 256>>>(N);
    convert_hist_kernel<<<(E + 255) / 256, 256>>>(ei32, E);
    scan1_kernel<<<nscan, 1024>>>(Ntot);
    scan2_kernel<<<1, 32>>>(nscan);
    scan3_kernel<<<nscan, 1024>>>(Ntot);
    scatter_kernel<<<(E + 255) / 256, 256>>>(E);

    dim3 ggrid(4, (N + 127) / 128);
    int attn_blocks = (N + 7) / 8;

    for (int layer = 0; layer < 2; layer++) {
        const float* xin = (layer == 0) ? x : nullptr;   // nullptr -> g_h
        gemm4_kernel<<<ggrid, 256>>>(xin,
            W[layer][0], W[layer][1], W[layer][2], W[layer][3],
            B[layer][0], B[layer][1], B[layer][2], B[layer][3], N);
        attn_gather_kernel<<<attn_blocks, 256>>>(
            layer == 0 ? nullptr : (float*)d_out, N, layer == 0 ? 1 : 0);
    }
}

// round 8
// speedup vs baseline: 3.4894x; 1.0752x over previous
#include <cuda_runtime.h>
#include <cuda_fp16.h>
#include <cstdint>

#define NMAX 50000
#define EMAX 800000
#define D 128
#define H 8
#define ATT_SCALE 0.25f   // 1/sqrt(16)
#define NEG_INF __int_as_float(0xff800000)

// ---------------- scratch (device globals; no runtime allocation) ----------
__device__ __align__(16) float  g_q[NMAX * D];
__device__ __align__(16) __half g_kh[NMAX * D];
__device__ __align__(16) __half g_vh[NMAX * D];
__device__ __align__(16) float  g_s[NMAX * D];
__device__ __align__(16) float  g_h[NMAX * D];    // inter-layer hidden
__device__ int   g_src[EMAX];
__device__ int   g_dst[EMAX];
__device__ int   g_rowptr[NMAX + 1];
__device__ int   g_cursor[NMAX + 1];
__device__ int   g_csrc[EMAX];                    // CSR: src node per incoming edge
__device__ int   g_blocksums[64];
__device__ int   g_is64;

// ---------------- edge_index dtype detection ------------------------------
__global__ void detect_kernel(const int* __restrict__ ei32)
{
    __shared__ int any_nonzero;
    if (threadIdx.x == 0) any_nonzero = 0;
    __syncthreads();
    int v = ei32[2 * threadIdx.x + 1];
    if (v != 0) any_nonzero = 1;
    __syncthreads();
    if (threadIdx.x == 0) g_is64 = any_nonzero ? 0 : 1;
}

__global__ void zero_cnt_kernel(int N)
{
    int i = blockIdx.x * blockDim.x + threadIdx.x;
    if (i <= N) g_rowptr[i] = 0;
}

// fused convert + histogram
__global__ void convert_hist_kernel(const int* __restrict__ ei32, int E)
{
    int e = blockIdx.x * blockDim.x + threadIdx.x;
    if (e >= E) return;
    int s, d;
    if (g_is64) {
        s = ei32[2 * (size_t)e];
        d = ei32[2 * ((size_t)E + e)];
    } else {
        s = ei32[e];
        d = ei32[(size_t)E + e];
    }
    g_src[e] = s;
    g_dst[e] = d;
    atomicAdd(&g_rowptr[d], 1);
}

// block-level exclusive scan: 1024 elements per block (in place on g_rowptr)
__global__ void scan1_kernel(int Ntot)
{
    __shared__ int sh[1024];
    int t = threadIdx.x;
    int i = blockIdx.x * 1024 + t;
    int v = (i < Ntot) ? g_rowptr[i] : 0;
    sh[t] = v;
    for (int off = 1; off < 1024; off <<= 1) {
        __syncthreads();
        int x = (t >= off) ? sh[t - off] : 0;
        __syncthreads();
        sh[t] += x;
    }
    __syncthreads();
    if (i < Ntot) g_rowptr[i] = sh[t] - v;      // exclusive
    if (t == 1023) g_blocksums[blockIdx.x] = sh[t];
}

__global__ void scan2_kernel(int nb)
{
    if (threadIdx.x == 0) {
        int acc = 0;
        for (int b = 0; b < nb; b++) {
            int x = g_blocksums[b];
            g_blocksums[b] = acc;
            acc += x;
        }
    }
}

__global__ void scan3_kernel(int Ntot)
{
    int i = blockIdx.x * 1024 + threadIdx.x;
    if (i < Ntot) {
        int r = g_rowptr[i] + g_blocksums[blockIdx.x];
        g_rowptr[i] = r;
        g_cursor[i] = r;
    }
}

__global__ void scatter_kernel(int E)
{
    int e = blockIdx.x * blockDim.x + threadIdx.x;
    if (e >= E) return;
    int pos = atomicAdd(&g_cursor[g_dst[e]], 1);
    g_csrc[pos] = g_src[e];
}

// ---------------- tf32 split helpers ----------------------------------------
__device__ __forceinline__ void split_tf32(float x, float& hi, float& lo)
{
    asm("cvt.rna.tf32.f32 %0, %1;" : "=f"(hi) : "f"(x));
    float r = x - hi;
    asm("cvt.rna.tf32.f32 %0, %1;" : "=f"(lo) : "f"(r));
}

__device__ __forceinline__ void mma_tf32(float* c, const uint32_t* a,
                                         uint32_t b0, uint32_t b1)
{
    asm volatile(
        "mma.sync.aligned.m16n8k8.row.col.f32.tf32.tf32.f32 "
        "{%0,%1,%2,%3}, {%4,%5,%6,%7}, {%8,%9}, {%0,%1,%2,%3};"
        : "+f"(c[0]), "+f"(c[1]), "+f"(c[2]), "+f"(c[3])
        : "r"(a[0]), "r"(a[1]), "r"(a[2]), "r"(a[3]), "r"(b0), "r"(b1));
}

// ---------------- fused GEMM: {q,k,v,s} = X @ W_i + b_i (tf32 tensor cores) -
// grid = (4, ceil(N/128)); block = 256 (8 warps, 4x2); warp tile 32x64
// split-tf32: Y = Ah*Bh + Ah*Bl + Al*Bh  (fp32-accurate)
// k (which==1) and v (which==2) outputs stored as fp16 for the gather phase
#define XS_PAD 20
#define WS_PAD 136

__global__ __launch_bounds__(256, 2) void gemm4_kernel(
    const float* __restrict__ Xin,
    const float* __restrict__ Wq, const float* __restrict__ Wk,
    const float* __restrict__ Wv, const float* __restrict__ Ws_,
    const float* __restrict__ bq, const float* __restrict__ bk,
    const float* __restrict__ bv, const float* __restrict__ bs,
    int N)
{
    const float* X = Xin ? Xin : g_h;
    int which = blockIdx.x;
    const float* W = (which == 0) ? Wq : (which == 1) ? Wk : (which == 2) ? Wv : Ws_;
    const float* bias = (which == 0) ? bq : (which == 1) ? bk : (which == 2) ? bv : bs;

    __shared__ float Xh[128][XS_PAD];
    __shared__ float Xl[128][XS_PAD];
    __shared__ float Wh[16][WS_PAD];
    __shared__ float Wl[16][WS_PAD];

    int tid  = threadIdx.x;
    int lane = tid & 31;
    int warp = tid >> 5;
    int wm   = warp & 3;          // m offset = wm*32
    int wn   = warp >> 2;         // n offset = wn*64
    int lx   = lane & 3;
    int ly   = lane >> 2;
    int row0 = blockIdx.y * 128;

    int xm[2], xc[2], wr[2], wc[2];
#pragma unroll
    for (int l = 0; l < 2; l++) {
        int f = tid + l * 256;
        xm[l] = f >> 2;
        xc[l] = (f & 3) * 4;
        wr[l] = f >> 5;
        wc[l] = (f & 31) * 4;
    }

    float acc[2][8][4];
#pragma unroll
    for (int i = 0; i < 2; i++)
#pragma unroll
        for (int j = 0; j < 8; j++)
#pragma unroll
            for (int t = 0; t < 4; t++) acc[i][j][t] = 0.f;

    // prefetch k-step 0
    float4 xv[2], wv[2];
#pragma unroll
    for (int l = 0; l < 2; l++) {
        int gr = row0 + xm[l];
        xv[l] = (gr < N) ? *(const float4*)(X + (size_t)gr * 128 + xc[l])
                         : make_float4(0.f, 0.f, 0.f, 0.f);
        wv[l] = *(const float4*)(W + (size_t)wr[l] * 128 + wc[l]);
    }

    for (int step = 0; step < 8; step++) {
#pragma unroll
        for (int l = 0; l < 2; l++) {
            float h0, l0, h1, l1, h2, l2, h3, l3;
            split_tf32(xv[l].x, h0, l0); split_tf32(xv[l].y, h1, l1);
            split_tf32(xv[l].z, h2, l2); split_tf32(xv[l].w, h3, l3);
            *(float4*)&Xh[xm[l]][xc[l]] = make_float4(h0, h1, h2, h3);
            *(float4*)&Xl[xm[l]][xc[l]] = make_float4(l0, l1, l2, l3);
            split_tf32(wv[l].x, h0, l0); split_tf32(wv[l].y, h1, l1);
            split_tf32(wv[l].z, h2, l2); split_tf32(wv[l].w, h3, l3);
            *(float4*)&Wh[wr[l]][wc[l]] = make_float4(h0, h1, h2, h3);
            *(float4*)&Wl[wr[l]][wc[l]] = make_float4(l0, l1, l2, l3);
        }
        __syncthreads();

        if (step < 7) {
            int kk = (step + 1) * 16;
#pragma unroll
            for (int l = 0; l < 2; l++) {
                int gr = row0 + xm[l];
                xv[l] = (gr < N) ? *(const float4*)(X + (size_t)gr * 128 + kk + xc[l])
                                 : make_float4(0.f, 0.f, 0.f, 0.f);
                wv[l] = *(const float4*)(W + (size_t)(kk + wr[l]) * 128 + wc[l]);
            }
        }

#pragma unroll
        for (int s = 0; s < 2; s++) {       // two k8 sub-steps
            uint32_t ah[2][4], al[2][4];
#pragma unroll
            for (int i = 0; i < 2; i++) {
                int r = wm * 32 + i * 16 + ly;
                int c = s * 8 + lx;
                ah[i][0] = __float_as_uint(Xh[r][c]);
                ah[i][1] = __float_as_uint(Xh[r + 8][c]);
                ah[i][2] = __float_as_uint(Xh[r][c + 4]);
                ah[i][3] = __float_as_uint(Xh[r + 8][c + 4]);
                al[i][0] = __float_as_uint(Xl[r][c]);
                al[i][1] = __float_as_uint(Xl[r + 8][c]);
                al[i][2] = __float_as_uint(Xl[r][c + 4]);
                al[i][3] = __float_as_uint(Xl[r + 8][c + 4]);
            }
#pragma unroll
            for (int j = 0; j < 8; j++) {
                int n = wn * 64 + j * 8 + ly;
                int kr = s * 8 + lx;
                uint32_t bh0 = __float_as_uint(Wh[kr][n]);
                uint32_t bh1 = __float_as_uint(Wh[kr + 4][n]);
                uint32_t bl0 = __float_as_uint(Wl[kr][n]);
                uint32_t bl1 = __float_as_uint(Wl[kr + 4][n]);
#pragma unroll
                for (int i = 0; i < 2; i++) {
                    mma_tf32(acc[i][j], ah[i], bh0, bh1);   // Ah*Bh
                    mma_tf32(acc[i][j], al[i], bh0, bh1);   // Al*Bh
                    mma_tf32(acc[i][j], ah[i], bl0, bl1);   // Ah*Bl
                }
            }
        }
        __syncthreads();
    }

    // epilogue: bias add + guarded store
    bool is_half = (which == 1) || (which == 2);
    float*  Yf = (which == 0) ? g_q : g_s;
    __half* Yh = (which == 1) ? g_kh : g_vh;

#pragma unroll
    for (int i = 0; i < 2; i++) {
        int rg = row0 + wm * 32 + i * 16 + ly;
#pragma unroll
        for (int j = 0; j < 8; j++) {
            int cg = wn * 64 + j * 8 + 2 * lx;
            float2 bb = *(const float2*)(bias + cg);
            float o00 = acc[i][j][0] + bb.x, o01 = acc[i][j][1] + bb.y;
            float o10 = acc[i][j][2] + bb.x, o11 = acc[i][j][3] + bb.y;
            if (is_half) {
                if (rg < N)
                    *(__half2*)(Yh + (size_t)rg * 128 + cg) = __floats2half2_rn(o00, o01);
                if (rg + 8 < N)
                    *(__half2*)(Yh + (size_t)(rg + 8) * 128 + cg) = __floats2half2_rn(o10, o11);
            } else {
                if (rg < N)
                    *(float2*)(Yf + (size_t)rg * 128 + cg) = make_float2(o00, o01);
                if (rg + 8 < N)
                    *(float2*)(Yf + (size_t)(rg + 8) * 128 + cg) = make_float2(o10, o11);
            }
        }
    }
}

// ---------------- fused attention: gather + online softmax + skip ----------
// one warp per dst node; lane holds 4 channels (head = lane>>2); edge loop x4
// k/v gathered as fp16 (8B per lane per row), math in fp32
__device__ __forceinline__ float4 ld_half4(const __half* base, int node, int lane)
{
    uint2 u = __ldg((const uint2*)(base + (size_t)node * D) + lane);
    float2 f01 = __half22float2(*reinterpret_cast<__half2*>(&u.x));
    float2 f23 = __half22float2(*reinterpret_cast<__half2*>(&u.y));
    return make_float4(f01.x, f01.y, f23.x, f23.y);
}

__device__ __forceinline__ float edge_dot(float4 qv, float4 kv)
{
    float p = qv.x * kv.x + qv.y * kv.y + qv.z * kv.z + qv.w * kv.w;
    p += __shfl_xor_sync(0xffffffffu, p, 1);
    p += __shfl_xor_sync(0xffffffffu, p, 2);
    return p * ATT_SCALE;
}

__global__ void attn_gather_kernel(float* __restrict__ outp, int N, int do_relu)
{
    int wg = blockIdx.x * 8 + (threadIdx.x >> 5);
    if (wg >= N) return;
    int lane = threadIdx.x & 31;
    size_t off = (size_t)wg * D;

    float4 qv = *((const float4*)(g_q + off) + lane);

    int beg = g_rowptr[wg];
    int end = g_rowptr[wg + 1];

    float m = NEG_INF;
    float den = 0.f;
    float4 acc = make_float4(0.f, 0.f, 0.f, 0.f);

    int i = beg;
    for (; i + 4 <= end; i += 4) {
        int s0 = __ldg(&g_csrc[i]);
        int s1 = __ldg(&g_csrc[i + 1]);
        int s2 = __ldg(&g_csrc[i + 2]);
        int s3 = __ldg(&g_csrc[i + 3]);
        float4 k0 = ld_half4(g_kh, s0, lane);
        float4 k1 = ld_half4(g_kh, s1, lane);
        float4 k2 = ld_half4(g_kh, s2, lane);
        float4 k3 = ld_half4(g_kh, s3, lane);
        float4 v0 = ld_half4(g_vh, s0, lane);
        float4 v1 = ld_half4(g_vh, s1, lane);
        float4 v2 = ld_half4(g_vh, s2, lane);
        float4 v3 = ld_half4(g_vh, s3, lane);

        float a0 = edge_dot(qv, k0);
        float a1 = edge_dot(qv, k1);
        float a2 = edge_dot(qv, k2);
        float a3 = edge_dot(qv, k3);

        float mx = fmaxf(fmaxf(a0, a1), fmaxf(a2, a3));
        float newm = fmaxf(m, mx);
        float c  = __expf(m - newm);        // first group: exp(-inf)=0
        float w0 = __expf(a0 - newm);
        float w1 = __expf(a1 - newm);
        float w2 = __expf(a2 - newm);
        float w3 = __expf(a3 - newm);
        den = den * c + (w0 + w1) + (w2 + w3);
        acc.x = acc.x * c + w0 * v0.x + w1 * v1.x + w2 * v2.x + w3 * v3.x;
        acc.y = acc.y * c + w0 * v0.y + w1 * v1.y + w2 * v2.y + w3 * v3.y;
        acc.z = acc.z * c + w0 * v0.z + w1 * v1.z + w2 * v2.z + w3 * v3.z;
        acc.w = acc.w * c + w0 * v0.w + w1 * v1.w + w2 * v2.w + w3 * v3.w;
        m = newm;
    }
    for (; i < end; i++) {
        int s = __ldg(&g_csrc[i]);
        float4 kv = ld_half4(g_kh, s, lane);
        float4 vv = ld_half4(g_vh, s, lane);
        float alpha = edge_dot(qv, kv);
        float newm = fmaxf(m, alpha);
        float c = __expf(m - newm);
        float w = __expf(alpha - newm);
        den = den * c + w;
        acc.x = acc.x * c + w * vv.x;
        acc.y = acc.y * c + w * vv.y;
        acc.z = acc.z * c + w * vv.z;
        acc.w = acc.w * c + w * vv.w;
        m = newm;
    }

    float4 sv = *((const float4*)(g_s + off) + lane);
    float inv = (den > 0.f) ? 1.f / den : 0.f;
    float4 o = make_float4(sv.x + acc.x * inv, sv.y + acc.y * inv,
                           sv.z + acc.z * inv, sv.w + acc.w * inv);
    if (do_relu) {
        o.x = fmaxf(o.x, 0.f); o.y = fmaxf(o.y, 0.f);
        o.z = fmaxf(o.z, 0.f); o.w = fmaxf(o.w, 0.f);
    }
    float* op = outp ? outp : g_h;
    *((float4*)(op + off) + lane) = o;
}

// ---------------- host ------------------------------------------------------
extern "C" void kernel_launch(void* const* d_in, const int* in_sizes, int n_in,
                              void* d_out, int out_size)
{
    const float* x = (const float*)d_in[0];
    const int* ei32 = (const int*)d_in[1];
    int N = in_sizes[0] / 128;
    int E = in_sizes[1] / 2;

    const float* W[2][4] = {
        {(const float*)d_in[3], (const float*)d_in[5], (const float*)d_in[7], (const float*)d_in[9]},
        {(const float*)d_in[11], (const float*)d_in[13], (const float*)d_in[15], (const float*)d_in[17]}
    };
    const float* B[2][4] = {
        {(const float*)d_in[4], (const float*)d_in[6], (const float*)d_in[8], (const float*)d_in[10]},
        {(const float*)d_in[12], (const float*)d_in[14], (const float*)d_in[16], (const float*)d_in[18]}
    };

    // one-time side stream + fork/join events (resources only; work is
    // identical on every call)
    static cudaStream_t s2 = nullptr;
    static cudaEvent_t evFork = nullptr, evJoin = nullptr;
    if (!s2) {
        cudaStreamCreateWithFlags(&s2, cudaStreamNonBlocking);
        cudaEventCreateWithFlags(&evFork, cudaEventDisableTiming);
        cudaEventCreateWithFlags(&evJoin, cudaEventDisableTiming);
    }

    int Ntot = N + 1;
    int nscan = (Ntot + 1023) / 1024;

    // fork: CSR build on s2, overlapped with layer-0 GEMM on the main stream
    cudaEventRecord(evFork, 0);
    cudaStreamWaitEvent(s2, evFork, 0);
    detect_kernel<<<1, 256, 0, s2>>>(ei32);
    zero_cnt_kernel<<<(Ntot + 255) / 256, 256, 0, s2>>>(N);
    convert_hist_kernel<<<(E + 255) / 256, 256, 0, s2>>>(ei32, E);
    scan1_kernel<<<nscan, 1024, 0, s2>>>(Ntot);
    scan2_kernel<<<1, 32, 0, s2>>>(nscan);
    scan3_kernel<<<nscan, 1024, 0, s2>>>(Ntot);
    scatter_kernel<<<(E + 255) / 256, 256, 0, s2>>>(E);
    cudaEventRecord(evJoin, s2);

    dim3 ggrid(4, (N + 127) / 128);
    int attn_blocks = (N + 7) / 8;

    // layer 0
    gemm4_kernel<<<ggrid, 256>>>(x,
        W[0][0], W[0][1], W[0][2], W[0][3],
        B[0][0], B[0][1], B[0][2], B[0][3], N);
    cudaStreamWaitEvent(0, evJoin, 0);   // join: attention needs CSR
    attn_gather_kernel<<<attn_blocks, 256>>>(nullptr, N, 1);

    // layer 1
    gemm4_kernel<<<ggrid, 256>>>(nullptr,
        W[1][0], W[1][1], W[1][2], W[1][3],
        B[1][0], B[1][1], B[1][2], B[1][3], N);
    attn_gather_kernel<<<attn_blocks, 256>>>((float*)d_out, N, 0);
}

// round 9
// speedup vs baseline: 4.2251x; 1.2108x over previous
#include <cuda_runtime.h>
#include <cuda_fp16.h>
#include <cuda_bf16.h>
#include <cstdint>

#define NMAX 50000
#define EMAX 800000
#define D 128
#define H 8
#define ATT_SCALE 0.25f   // 1/sqrt(16)
#define NEG_INF __int_as_float(0xff800000)

// ---------------- scratch (device globals; no runtime allocation) ----------
__device__ __align__(16) float  g_q[NMAX * D];
__device__ __align__(16) __half g_kh[NMAX * D];
__device__ __align__(16) __half g_vh[NMAX * D];
__device__ __align__(16) float  g_s[NMAX * D];
__device__ __align__(16) float  g_h[NMAX * D];    // inter-layer hidden
__device__ int   g_src[EMAX];
__device__ int   g_dst[EMAX];
__device__ int   g_rowptr[NMAX + 1];
__device__ int   g_cursor[NMAX + 1];
__device__ int   g_csrc[EMAX];                    // CSR: src node per incoming edge
__device__ int   g_blocksums[64];
__device__ int   g_is64;

// ---------------- edge_index dtype detection ------------------------------
__global__ void detect_kernel(const int* __restrict__ ei32)
{
    __shared__ int any_nonzero;
    if (threadIdx.x == 0) any_nonzero = 0;
    __syncthreads();
    int v = ei32[2 * threadIdx.x + 1];
    if (v != 0) any_nonzero = 1;
    __syncthreads();
    if (threadIdx.x == 0) g_is64 = any_nonzero ? 0 : 1;
}

__global__ void zero_cnt_kernel(int N)
{
    int i = blockIdx.x * blockDim.x + threadIdx.x;
    if (i <= N) g_rowptr[i] = 0;
}

// fused convert + histogram
__global__ void convert_hist_kernel(const int* __restrict__ ei32, int E)
{
    int e = blockIdx.x * blockDim.x + threadIdx.x;
    if (e >= E) return;
    int s, d;
    if (g_is64) {
        s = ei32[2 * (size_t)e];
        d = ei32[2 * ((size_t)E + e)];
    } else {
        s = ei32[e];
        d = ei32[(size_t)E + e];
    }
    g_src[e] = s;
    g_dst[e] = d;
    atomicAdd(&g_rowptr[d], 1);
}

// block-level exclusive scan: 1024 elements per block (in place on g_rowptr)
__global__ void scan1_kernel(int Ntot)
{
    __shared__ int sh[1024];
    int t = threadIdx.x;
    int i = blockIdx.x * 1024 + t;
    int v = (i < Ntot) ? g_rowptr[i] : 0;
    sh[t] = v;
    for (int off = 1; off < 1024; off <<= 1) {
        __syncthreads();
        int x = (t >= off) ? sh[t - off] : 0;
        __syncthreads();
        sh[t] += x;
    }
    __syncthreads();
    if (i < Ntot) g_rowptr[i] = sh[t] - v;      // exclusive
    if (t == 1023) g_blocksums[blockIdx.x] = sh[t];
}

__global__ void scan2_kernel(int nb)
{
    if (threadIdx.x == 0) {
        int acc = 0;
        for (int b = 0; b < nb; b++) {
            int x = g_blocksums[b];
            g_blocksums[b] = acc;
            acc += x;
        }
    }
}

__global__ void scan3_kernel(int Ntot)
{
    int i = blockIdx.x * 1024 + threadIdx.x;
    if (i < Ntot) {
        int r = g_rowptr[i] + g_blocksums[blockIdx.x];
        g_rowptr[i] = r;
        g_cursor[i] = r;
    }
}

__global__ void scatter_kernel(int E)
{
    int e = blockIdx.x * blockDim.x + threadIdx.x;
    if (e >= E) return;
    int pos = atomicAdd(&g_cursor[g_dst[e]], 1);
    g_csrc[pos] = g_src[e];
}

// ---------------- bf16 split helpers ----------------------------------------
__device__ __forceinline__ void split_bf16(float x, __nv_bfloat16& hi, __nv_bfloat16& lo)
{
    hi = __float2bfloat16_rn(x);
    lo = __float2bfloat16_rn(x - __bfloat162float(hi));
}

__device__ __forceinline__ uint32_t pack_bf16(__nv_bfloat16 a, __nv_bfloat16 b)
{
    __nv_bfloat162 p = __nv_bfloat162(a, b);   // a in low 16 bits
    return *reinterpret_cast<uint32_t*>(&p);
}

__device__ __forceinline__ void mma_bf16(float* c, const uint32_t* a,
                                         uint32_t b0, uint32_t b1)
{
    asm volatile(
        "mma.sync.aligned.m16n8k16.row.col.f32.bf16.bf16.f32 "
        "{%0,%1,%2,%3}, {%4,%5,%6,%7}, {%8,%9}, {%0,%1,%2,%3};"
        : "+f"(c[0]), "+f"(c[1]), "+f"(c[2]), "+f"(c[3])
        : "r"(a[0]), "r"(a[1]), "r"(a[2]), "r"(a[3]), "r"(b0), "r"(b1));
}

// ---------------- fused GEMM: {q,k,v,s} = X @ W_i + b_i (bf16-split MMA) ----
// grid = (4, ceil(N/128)); block = 256 (8 warps, 4x2); warp tile 32x64
// 2-way bf16 split: Y = Ah*Bh + Al*Bh + Ah*Bl  (~1e-5 accurate)
// smem holds k-PAIR-packed 32-bit words matching m16n8k16 fragment layout.
#define XPW 12    // words per X row (8 pairs + pad) -> conflict-free frags
#define WPW 132   // words per W pair-row (128 + pad) -> conflict-free frags

__global__ __launch_bounds__(256, 2) void gemm4_kernel(
    const float* __restrict__ Xin,
    const float* __restrict__ Wq, const float* __restrict__ Wk,
    const float* __restrict__ Wv, const float* __restrict__ Ws_,
    const float* __restrict__ bq, const float* __restrict__ bk,
    const float* __restrict__ bv, const float* __restrict__ bs,
    int N)
{
    const float* X = Xin ? Xin : g_h;
    int which = blockIdx.x;
    const float* W = (which == 0) ? Wq : (which == 1) ? Wk : (which == 2) ? Wv : Ws_;
    const float* bias = (which == 0) ? bq : (which == 1) ? bk : (which == 2) ? bv : bs;

    __shared__ uint32_t Xph[128 * XPW];
    __shared__ uint32_t Xpl[128 * XPW];
    __shared__ uint32_t Wph[8 * WPW];
    __shared__ uint32_t Wpl[8 * WPW];

    int tid  = threadIdx.x;
    int lane = tid & 31;
    int warp = tid >> 5;
    int wm   = warp & 3;          // m offset = wm*32
    int wn   = warp >> 2;         // n offset = wn*64
    int lx   = lane & 3;          // threadID_in_group (t)
    int ly   = lane >> 2;         // groupID (g)
    int row0 = blockIdx.y * 128;

    // X loader coords: 2 float4 per thread per step (m, 4 consecutive k)
    int xm[2], xc[2];
#pragma unroll
    for (int l = 0; l < 2; l++) {
        int f = tid + l * 256;
        xm[l] = f >> 2;
        xc[l] = (f & 3) * 4;
    }
    // W loader coords: one (k-pair, 4n) chunk per thread per step
    int wkp = tid >> 5;           // pair index 0..7
    int wn0 = (tid & 31) * 4;     // 4 consecutive n

    float acc[2][8][4];
#pragma unroll
    for (int i = 0; i < 2; i++)
#pragma unroll
        for (int j = 0; j < 8; j++)
#pragma unroll
            for (int t = 0; t < 4; t++) acc[i][j][t] = 0.f;

    // prefetch k-step 0
    float4 xv[2], wv0, wv1;
#pragma unroll
    for (int l = 0; l < 2; l++) {
        int gr = row0 + xm[l];
        xv[l] = (gr < N) ? *(const float4*)(X + (size_t)gr * 128 + xc[l])
                         : make_float4(0.f, 0.f, 0.f, 0.f);
    }
    wv0 = *(const float4*)(W + (size_t)(2 * wkp) * 128 + wn0);
    wv1 = *(const float4*)(W + (size_t)(2 * wkp + 1) * 128 + wn0);

    for (int step = 0; step < 8; step++) {
        // split + pack + store current tile
#pragma unroll
        for (int l = 0; l < 2; l++) {
            __nv_bfloat16 h0, l0, h1, l1, h2, l2, h3, l3;
            split_bf16(xv[l].x, h0, l0); split_bf16(xv[l].y, h1, l1);
            split_bf16(xv[l].z, h2, l2); split_bf16(xv[l].w, h3, l3);
            int base = xm[l] * XPW + (xc[l] >> 1);
            Xph[base]     = pack_bf16(h0, h1);
            Xph[base + 1] = pack_bf16(h2, h3);
            Xpl[base]     = pack_bf16(l0, l1);
            Xpl[base + 1] = pack_bf16(l2, l3);
        }
        {
            __nv_bfloat16 ah[4], al[4], bh[4], bl[4];
            split_bf16(wv0.x, ah[0], al[0]); split_bf16(wv0.y, ah[1], al[1]);
            split_bf16(wv0.z, ah[2], al[2]); split_bf16(wv0.w, ah[3], al[3]);
            split_bf16(wv1.x, bh[0], bl[0]); split_bf16(wv1.y, bh[1], bl[1]);
            split_bf16(wv1.z, bh[2], bl[2]); split_bf16(wv1.w, bh[3], bl[3]);
            int base = wkp * WPW + wn0;
#pragma unroll
            for (int j = 0; j < 4; j++) {
                Wph[base + j] = pack_bf16(ah[j], bh[j]);   // {W[2kp][n], W[2kp+1][n]}
                Wpl[base + j] = pack_bf16(al[j], bl[j]);
            }
        }
        __syncthreads();

        // prefetch next tile (overlaps with MMA below)
        if (step < 7) {
            int kk = (step + 1) * 16;
#pragma unroll
            for (int l = 0; l < 2; l++) {
                int gr = row0 + xm[l];
                xv[l] = (gr < N) ? *(const float4*)(X + (size_t)gr * 128 + kk + xc[l])
                                 : make_float4(0.f, 0.f, 0.f, 0.f);
            }
            wv0 = *(const float4*)(W + (size_t)(kk + 2 * wkp) * 128 + wn0);
            wv1 = *(const float4*)(W + (size_t)(kk + 2 * wkp + 1) * 128 + wn0);
        }

        // one k16 MMA step
        uint32_t ah[2][4], al[2][4];
#pragma unroll
        for (int i = 0; i < 2; i++) {
            int r = wm * 32 + i * 16 + ly;
            ah[i][0] = Xph[r * XPW + lx];
            ah[i][1] = Xph[(r + 8) * XPW + lx];
            ah[i][2] = Xph[r * XPW + lx + 4];
            ah[i][3] = Xph[(r + 8) * XPW + lx + 4];
            al[i][0] = Xpl[r * XPW + lx];
            al[i][1] = Xpl[(r + 8) * XPW + lx];
            al[i][2] = Xpl[r * XPW + lx + 4];
            al[i][3] = Xpl[(r + 8) * XPW + lx + 4];
        }
#pragma unroll
        for (int j = 0; j < 8; j++) {
            int n = wn * 64 + j * 8 + ly;
            uint32_t bh0 = Wph[lx * WPW + n];
            uint32_t bh1 = Wph[(lx + 4) * WPW + n];
            uint32_t bl0 = Wpl[lx * WPW + n];
            uint32_t bl1 = Wpl[(lx + 4) * WPW + n];
#pragma unroll
            for (int i = 0; i < 2; i++) {
                mma_bf16(acc[i][j], ah[i], bh0, bh1);   // Ah*Bh
                mma_bf16(acc[i][j], al[i], bh0, bh1);   // Al*Bh
                mma_bf16(acc[i][j], ah[i], bl0, bl1);   // Ah*Bl
            }
        }
        __syncthreads();
    }

    // epilogue: bias add + guarded store (c0,c1 at row; c2,c3 at row+8)
    bool is_half = (which == 1) || (which == 2);
    float*  Yf = (which == 0) ? g_q : g_s;
    __half* Yh = (which == 1) ? g_kh : g_vh;

#pragma unroll
    for (int i = 0; i < 2; i++) {
        int rg = row0 + wm * 32 + i * 16 + ly;
#pragma unroll
        for (int j = 0; j < 8; j++) {
            int cg = wn * 64 + j * 8 + 2 * lx;
            float2 bb = *(const float2*)(bias + cg);
            float o00 = acc[i][j][0] + bb.x, o01 = acc[i][j][1] + bb.y;
            float o10 = acc[i][j][2] + bb.x, o11 = acc[i][j][3] + bb.y;
            if (is_half) {
                if (rg < N)
                    *(__half2*)(Yh + (size_t)rg * 128 + cg) = __floats2half2_rn(o00, o01);
                if (rg + 8 < N)
                    *(__half2*)(Yh + (size_t)(rg + 8) * 128 + cg) = __floats2half2_rn(o10, o11);
            } else {
                if (rg < N)
                    *(float2*)(Yf + (size_t)rg * 128 + cg) = make_float2(o00, o01);
                if (rg + 8 < N)
                    *(float2*)(Yf + (size_t)(rg + 8) * 128 + cg) = make_float2(o10, o11);
            }
        }
    }
}

// ---------------- fused attention: gather + online softmax + skip ----------
// one warp per dst node; lane holds 4 channels (head = lane>>2); edge loop x4
// k/v gathered as fp16 (8B per lane per row), math in fp32
__device__ __forceinline__ float4 ld_half4(const __half* base, int node, int lane)
{
    uint2 u = __ldg((const uint2*)(base + (size_t)node * D) + lane);
    float2 f01 = __half22float2(*reinterpret_cast<__half2*>(&u.x));
    float2 f23 = __half22float2(*reinterpret_cast<__half2*>(&u.y));
    return make_float4(f01.x, f01.y, f23.x, f23.y);
}

__device__ __forceinline__ float edge_dot(float4 qv, float4 kv)
{
    float p = qv.x * kv.x + qv.y * kv.y + qv.z * kv.z + qv.w * kv.w;
    p += __shfl_xor_sync(0xffffffffu, p, 1);
    p += __shfl_xor_sync(0xffffffffu, p, 2);
    return p * ATT_SCALE;
}

__global__ void attn_gather_kernel(float* __restrict__ outp, int N, int do_relu)
{
    int wg = blockIdx.x * 8 + (threadIdx.x >> 5);
    if (wg >= N) return;
    int lane = threadIdx.x & 31;
    size_t off = (size_t)wg * D;

    float4 qv = *((const float4*)(g_q + off) + lane);

    int beg = g_rowptr[wg];
    int end = g_rowptr[wg + 1];

    float m = NEG_INF;
    float den = 0.f;
    float4 acc = make_float4(0.f, 0.f, 0.f, 0.f);

    int i = beg;
    for (; i + 4 <= end; i += 4) {
        int s0 = __ldg(&g_csrc[i]);
        int s1 = __ldg(&g_csrc[i + 1]);
        int s2 = __ldg(&g_csrc[i + 2]);
        int s3 = __ldg(&g_csrc[i + 3]);
        float4 k0 = ld_half4(g_kh, s0, lane);
        float4 k1 = ld_half4(g_kh, s1, lane);
        float4 k2 = ld_half4(g_kh, s2, lane);
        float4 k3 = ld_half4(g_kh, s3, lane);
        float4 v0 = ld_half4(g_vh, s0, lane);
        float4 v1 = ld_half4(g_vh, s1, lane);
        float4 v2 = ld_half4(g_vh, s2, lane);
        float4 v3 = ld_half4(g_vh, s3, lane);

        float a0 = edge_dot(qv, k0);
        float a1 = edge_dot(qv, k1);
        float a2 = edge_dot(qv, k2);
        float a3 = edge_dot(qv, k3);

        float mx = fmaxf(fmaxf(a0, a1), fmaxf(a2, a3));
        float newm = fmaxf(m, mx);
        float c  = __expf(m - newm);        // first group: exp(-inf)=0
        float w0 = __expf(a0 - newm);
        float w1 = __expf(a1 - newm);
        float w2 = __expf(a2 - newm);
        float w3 = __expf(a3 - newm);
        den = den * c + (w0 + w1) + (w2 + w3);
        acc.x = acc.x * c + w0 * v0.x + w1 * v1.x + w2 * v2.x + w3 * v3.x;
        acc.y = acc.y * c + w0 * v0.y + w1 * v1.y + w2 * v2.y + w3 * v3.y;
        acc.z = acc.z * c + w0 * v0.z + w1 * v1.z + w2 * v2.z + w3 * v3.z;
        acc.w = acc.w * c + w0 * v0.w + w1 * v1.w + w2 * v2.w + w3 * v3.w;
        m = newm;
    }
    for (; i < end; i++) {
        int s = __ldg(&g_csrc[i]);
        float4 kv = ld_half4(g_kh, s, lane);
        float4 vv = ld_half4(g_vh, s, lane);
        float alpha = edge_dot(qv, kv);
        float newm = fmaxf(m, alpha);
        float c = __expf(m - newm);
        float w = __expf(alpha - newm);
        den = den * c + w;
        acc.x = acc.x * c + w * vv.x;
        acc.y = acc.y * c + w * vv.y;
        acc.z = acc.z * c + w * vv.z;
        acc.w = acc.w * c + w * vv.w;
        m = newm;
    }

    float4 sv = *((const float4*)(g_s + off) + lane);
    float inv = (den > 0.f) ? 1.f / den : 0.f;
    float4 o = make_float4(sv.x + acc.x * inv, sv.y + acc.y * inv,
                           sv.z + acc.z * inv, sv.w + acc.w * inv);
    if (do_relu) {
        o.x = fmaxf(o.x, 0.f); o.y = fmaxf(o.y, 0.f);
        o.z = fmaxf(o.z, 0.f); o.w = fmaxf(o.w, 0.f);
    }
    float* op = outp ? outp : g_h;
    *((float4*)(op + off) + lane) = o;
}

// ---------------- host ------------------------------------------------------
extern "C" void kernel_launch(void* const* d_in, const int* in_sizes, int n_in,
                              void* d_out, int out_size)
{
    const float* x = (const float*)d_in[0];
    const int* ei32 = (const int*)d_in[1];
    int N = in_sizes[0] / 128;
    int E = in_sizes[1] / 2;

    const float* W[2][4] = {
        {(const float*)d_in[3], (const float*)d_in[5], (const float*)d_in[7], (const float*)d_in[9]},
        {(const float*)d_in[11], (const float*)d_in[13], (const float*)d_in[15], (const float*)d_in[17]}
    };
    const float* B[2][4] = {
        {(const float*)d_in[4], (const float*)d_in[6], (const float*)d_in[8], (const float*)d_in[10]},
        {(const float*)d_in[12], (const float*)d_in[14], (const float*)d_in[16], (const float*)d_in[18]}
    };

    // one-time side stream + fork/join events (resources only; work is
    // identical on every call)
    static cudaStream_t s2 = nullptr;
    static cudaEvent_t evFork = nullptr, evJoin = nullptr;
    if (!s2) {
        cudaStreamCreateWithFlags(&s2, cudaStreamNonBlocking);
        cudaEventCreateWithFlags(&evFork, cudaEventDisableTiming);
        cudaEventCreateWithFlags(&evJoin, cudaEventDisableTiming);
    }

    int Ntot = N + 1;
    int nscan = (Ntot + 1023) / 1024;

    // fork: CSR build on s2, overlapped with layer-0 GEMM on the main stream
    cudaEventRecord(evFork, 0);
    cudaStreamWaitEvent(s2, evFork, 0);
    detect_kernel<<<1, 256, 0, s2>>>(ei32);
    zero_cnt_kernel<<<(Ntot + 255) / 256, 256, 0, s2>>>(N);
    convert_hist_kernel<<<(E + 255) / 256, 256, 0, s2>>>(ei32, E);
    scan1_kernel<<<nscan, 1024, 0, s2>>>(Ntot);
    scan2_kernel<<<1, 32, 0, s2>>>(nscan);
    scan3_kernel<<<nscan, 1024, 0, s2>>>(Ntot);
    scatter_kernel<<<(E + 255) / 256, 256, 0, s2>>>(E);
    cudaEventRecord(evJoin, s2);

    dim3 ggrid(4, (N + 127) / 128);
    int attn_blocks = (N + 7) / 8;

    // layer 0
    gemm4_kernel<<<ggrid, 256>>>(x,
        W[0][0], W[0][1], W[0][2], W[0][3],
        B[0][0], B[0][1], B[0][2], B[0][3], N);
    cudaStreamWaitEvent(0, evJoin, 0);   // join: attention needs CSR
    attn_gather_kernel<<<attn_blocks, 256>>>(nullptr, N, 1);

    // layer 1
    gemm4_kernel<<<ggrid, 256>>>(nullptr,
        W[1][0], W[1][1], W[1][2], W[1][3],
        B[1][0], B[1][1], B[1][2], B[1][3], N);
    attn_gather_kernel<<<attn_blocks, 256>>>((float*)d_out, N, 0);
}

// round 10
// speedup vs baseline: 4.4986x; 1.0647x over previous
#include <cuda_runtime.h>
#include <cuda_fp16.h>
#include <cuda_bf16.h>
#include <cstdint>

#define NMAX 50000
#define EMAX 800000
#define D 128
#define H 8
#define ATT_SCALE 0.25f   // 1/sqrt(16)
#define NEG_INF __int_as_float(0xff800000)

// ---------------- scratch (device globals; no runtime allocation) ----------
__device__ __align__(16) float  g_q[NMAX * D];
__device__ __align__(16) __half g_kh[NMAX * D];
__device__ __align__(16) __half g_vh[NMAX * D];
__device__ __align__(16) float  g_s[NMAX * D];
__device__ __align__(16) float  g_h[NMAX * D];    // inter-layer hidden
__device__ int   g_src[EMAX];
__device__ int   g_dst[EMAX];
__device__ int   g_rowptr[NMAX + 1];
__device__ int   g_cursor[NMAX + 1];
__device__ int   g_csrc[EMAX];                    // CSR: src node per incoming edge
__device__ int   g_blocksums[64];
__device__ int   g_is64;

// ---------------- edge_index dtype detection ------------------------------
__global__ void detect_kernel(const int* __restrict__ ei32)
{
    __shared__ int any_nonzero;
    if (threadIdx.x == 0) any_nonzero = 0;
    __syncthreads();
    int v = ei32[2 * threadIdx.x + 1];
    if (v != 0) any_nonzero = 1;
    __syncthreads();
    if (threadIdx.x == 0) g_is64 = any_nonzero ? 0 : 1;
}

__global__ void zero_cnt_kernel(int N)
{
    int i = blockIdx.x * blockDim.x + threadIdx.x;
    if (i <= N) g_rowptr[i] = 0;
}

// fused convert + histogram
__global__ void convert_hist_kernel(const int* __restrict__ ei32, int E)
{
    int e = blockIdx.x * blockDim.x + threadIdx.x;
    if (e >= E) return;
    int s, d;
    if (g_is64) {
        s = ei32[2 * (size_t)e];
        d = ei32[2 * ((size_t)E + e)];
    } else {
        s = ei32[e];
        d = ei32[(size_t)E + e];
    }
    g_src[e] = s;
    g_dst[e] = d;
    atomicAdd(&g_rowptr[d], 1);
}

// block-level exclusive scan: 1024 elements per block (in place on g_rowptr)
__global__ void scan1_kernel(int Ntot)
{
    __shared__ int sh[1024];
    int t = threadIdx.x;
    int i = blockIdx.x * 1024 + t;
    int v = (i < Ntot) ? g_rowptr[i] : 0;
    sh[t] = v;
    for (int off = 1; off < 1024; off <<= 1) {
        __syncthreads();
        int x = (t >= off) ? sh[t - off] : 0;
        __syncthreads();
        sh[t] += x;
    }
    __syncthreads();
    if (i < Ntot) g_rowptr[i] = sh[t] - v;      // exclusive
    if (t == 1023) g_blocksums[blockIdx.x] = sh[t];
}

__global__ void scan2_kernel(int nb)
{
    if (threadIdx.x == 0) {
        int acc = 0;
        for (int b = 0; b < nb; b++) {
            int x = g_blocksums[b];
            g_blocksums[b] = acc;
            acc += x;
        }
    }
}

__global__ void scan3_kernel(int Ntot)
{
    int i = blockIdx.x * 1024 + threadIdx.x;
    if (i < Ntot) {
        int r = g_rowptr[i] + g_blocksums[blockIdx.x];
        g_rowptr[i] = r;
        g_cursor[i] = r;
    }
}

__global__ void scatter_kernel(int E)
{
    int e = blockIdx.x * blockDim.x + threadIdx.x;
    if (e >= E) return;
    int pos = atomicAdd(&g_cursor[g_dst[e]], 1);
    g_csrc[pos] = g_src[e];
}

// ---------------- bf16 split helpers ----------------------------------------
__device__ __forceinline__ void split_bf16(float x, __nv_bfloat16& hi, __nv_bfloat16& lo)
{
    hi = __float2bfloat16_rn(x);
    lo = __float2bfloat16_rn(x - __bfloat162float(hi));
}

__device__ __forceinline__ uint32_t pack_bf16(__nv_bfloat16 a, __nv_bfloat16 b)
{
    __nv_bfloat162 p = __nv_bfloat162(a, b);   // a in low 16 bits
    return *reinterpret_cast<uint32_t*>(&p);
}

__device__ __forceinline__ void mma_bf16(float* c, const uint32_t* a,
                                         uint32_t b0, uint32_t b1)
{
    asm volatile(
        "mma.sync.aligned.m16n8k16.row.col.f32.bf16.bf16.f32 "
        "{%0,%1,%2,%3}, {%4,%5,%6,%7}, {%8,%9}, {%0,%1,%2,%3};"
        : "+f"(c[0]), "+f"(c[1]), "+f"(c[2]), "+f"(c[3])
        : "r"(a[0]), "r"(a[1]), "r"(a[2]), "r"(a[3]), "r"(b0), "r"(b1));
}

// ---------------- fused GEMM: {q,k,v,s} = X @ W_i + b_i (bf16-split MMA) ----
// grid = (4, ceil(N/128)); block = 256 (8 warps, 4x2); warp tile 32x64
// 2-way bf16 split: Y = Ah*Bh + Al*Bh + Ah*Bl  (~1e-5 accurate)
// DOUBLE-BUFFERED smem, one __syncthreads per k-step.
#define XPW 12    // words per X row (8 pairs + pad) -> conflict-free frags
#define WPW 132   // words per W pair-row (128 + pad) -> conflict-free frags

__global__ __launch_bounds__(256, 2) void gemm4_kernel(
    const float* __restrict__ Xin,
    const float* __restrict__ Wq, const float* __restrict__ Wk,
    const float* __restrict__ Wv, const float* __restrict__ Ws_,
    const float* __restrict__ bq, const float* __restrict__ bk,
    const float* __restrict__ bv, const float* __restrict__ bs,
    int N)
{
    const float* X = Xin ? Xin : g_h;
    int which = blockIdx.x;
    const float* W = (which == 0) ? Wq : (which == 1) ? Wk : (which == 2) ? Wv : Ws_;
    const float* bias = (which == 0) ? bq : (which == 1) ? bk : (which == 2) ? bv : bs;

    __shared__ uint32_t Xph[2][128 * XPW];
    __shared__ uint32_t Xpl[2][128 * XPW];
    __shared__ uint32_t Wph[2][8 * WPW];
    __shared__ uint32_t Wpl[2][8 * WPW];

    int tid  = threadIdx.x;
    int lane = tid & 31;
    int warp = tid >> 5;
    int wm   = warp & 3;          // m offset = wm*32
    int wn   = warp >> 2;         // n offset = wn*64
    int lx   = lane & 3;          // threadID_in_group (t)
    int ly   = lane >> 2;         // groupID (g)
    int row0 = blockIdx.y * 128;

    // X loader coords: 2 float4 per thread per step (m, 4 consecutive k)
    int xm[2], xc[2];
#pragma unroll
    for (int l = 0; l < 2; l++) {
        int f = tid + l * 256;
        xm[l] = f >> 2;
        xc[l] = (f & 3) * 4;
    }
    // W loader coords: one (k-pair, 4n) chunk per thread per step
    int wkp = tid >> 5;           // pair index 0..7
    int wn0 = (tid & 31) * 4;     // 4 consecutive n

    float acc[2][8][4];
#pragma unroll
    for (int i = 0; i < 2; i++)
#pragma unroll
        for (int j = 0; j < 8; j++)
#pragma unroll
            for (int t = 0; t < 4; t++) acc[i][j][t] = 0.f;

    float4 xv[2], wv0, wv1;

    // load + split + store k-step 0 into buffer 0
#pragma unroll
    for (int l = 0; l < 2; l++) {
        int gr = row0 + xm[l];
        xv[l] = (gr < N) ? *(const float4*)(X + (size_t)gr * 128 + xc[l])
                         : make_float4(0.f, 0.f, 0.f, 0.f);
    }
    wv0 = *(const float4*)(W + (size_t)(2 * wkp) * 128 + wn0);
    wv1 = *(const float4*)(W + (size_t)(2 * wkp + 1) * 128 + wn0);
#pragma unroll
    for (int l = 0; l < 2; l++) {
        __nv_bfloat16 h0, l0, h1, l1, h2, l2, h3, l3;
        split_bf16(xv[l].x, h0, l0); split_bf16(xv[l].y, h1, l1);
        split_bf16(xv[l].z, h2, l2); split_bf16(xv[l].w, h3, l3);
        int base = xm[l] * XPW + (xc[l] >> 1);
        Xph[0][base]     = pack_bf16(h0, h1);
        Xph[0][base + 1] = pack_bf16(h2, h3);
        Xpl[0][base]     = pack_bf16(l0, l1);
        Xpl[0][base + 1] = pack_bf16(l2, l3);
    }
    {
        __nv_bfloat16 ah[4], al[4], bh[4], bl[4];
        split_bf16(wv0.x, ah[0], al[0]); split_bf16(wv0.y, ah[1], al[1]);
        split_bf16(wv0.z, ah[2], al[2]); split_bf16(wv0.w, ah[3], al[3]);
        split_bf16(wv1.x, bh[0], bl[0]); split_bf16(wv1.y, bh[1], bl[1]);
        split_bf16(wv1.z, bh[2], bl[2]); split_bf16(wv1.w, bh[3], bl[3]);
        int base = wkp * WPW + wn0;
#pragma unroll
        for (int j = 0; j < 4; j++) {
            Wph[0][base + j] = pack_bf16(ah[j], bh[j]);
            Wpl[0][base + j] = pack_bf16(al[j], bl[j]);
        }
    }
    __syncthreads();

    for (int step = 0; step < 8; step++) {
        int cur = step & 1;
        int nxt = cur ^ 1;

        // issue next tile's global loads (latency hidden under MMA)
        if (step < 7) {
            int kk = (step + 1) * 16;
#pragma unroll
            for (int l = 0; l < 2; l++) {
                int gr = row0 + xm[l];
                xv[l] = (gr < N) ? *(const float4*)(X + (size_t)gr * 128 + kk + xc[l])
                                 : make_float4(0.f, 0.f, 0.f, 0.f);
            }
            wv0 = *(const float4*)(W + (size_t)(kk + 2 * wkp) * 128 + wn0);
            wv1 = *(const float4*)(W + (size_t)(kk + 2 * wkp + 1) * 128 + wn0);
        }

        // one k16 MMA step from buf[cur]
        uint32_t ah[2][4], al[2][4];
#pragma unroll
        for (int i = 0; i < 2; i++) {
            int r = wm * 32 + i * 16 + ly;
            ah[i][0] = Xph[cur][r * XPW + lx];
            ah[i][1] = Xph[cur][(r + 8) * XPW + lx];
            ah[i][2] = Xph[cur][r * XPW + lx + 4];
            ah[i][3] = Xph[cur][(r + 8) * XPW + lx + 4];
            al[i][0] = Xpl[cur][r * XPW + lx];
            al[i][1] = Xpl[cur][(r + 8) * XPW + lx];
            al[i][2] = Xpl[cur][r * XPW + lx + 4];
            al[i][3] = Xpl[cur][(r + 8) * XPW + lx + 4];
        }
#pragma unroll
        for (int j = 0; j < 8; j++) {
            int n = wn * 64 + j * 8 + ly;
            uint32_t bh0 = Wph[cur][lx * WPW + n];
            uint32_t bh1 = Wph[cur][(lx + 4) * WPW + n];
            uint32_t bl0 = Wpl[cur][lx * WPW + n];
            uint32_t bl1 = Wpl[cur][(lx + 4) * WPW + n];
#pragma unroll
            for (int i = 0; i < 2; i++) {
                mma_bf16(acc[i][j], ah[i], bh0, bh1);   // Ah*Bh
                mma_bf16(acc[i][j], al[i], bh0, bh1);   // Al*Bh
                mma_bf16(acc[i][j], ah[i], bl0, bl1);   // Ah*Bl
            }
        }

        // split + store next tile into buf[nxt] (no clash with buf[cur] reads)
        if (step < 7) {
#pragma unroll
            for (int l = 0; l < 2; l++) {
                __nv_bfloat16 h0, l0, h1, l1, h2, l2, h3, l3;
                split_bf16(xv[l].x, h0, l0); split_bf16(xv[l].y, h1, l1);
                split_bf16(xv[l].z, h2, l2); split_bf16(xv[l].w, h3, l3);
                int base = xm[l] * XPW + (xc[l] >> 1);
                Xph[nxt][base]     = pack_bf16(h0, h1);
                Xph[nxt][base + 1] = pack_bf16(h2, h3);
                Xpl[nxt][base]     = pack_bf16(l0, l1);
                Xpl[nxt][base + 1] = pack_bf16(l2, l3);
            }
            __nv_bfloat16 ah2[4], al2[4], bh2[4], bl2[4];
            split_bf16(wv0.x, ah2[0], al2[0]); split_bf16(wv0.y, ah2[1], al2[1]);
            split_bf16(wv0.z, ah2[2], al2[2]); split_bf16(wv0.w, ah2[3], al2[3]);
            split_bf16(wv1.x, bh2[0], bl2[0]); split_bf16(wv1.y, bh2[1], bl2[1]);
            split_bf16(wv1.z, bh2[2], bl2[2]); split_bf16(wv1.w, bh2[3], bl2[3]);
            int base = wkp * WPW + wn0;
#pragma unroll
            for (int j = 0; j < 4; j++) {
                Wph[nxt][base + j] = pack_bf16(ah2[j], bh2[j]);
                Wpl[nxt][base + j] = pack_bf16(al2[j], bl2[j]);
            }
        }
        __syncthreads();
    }

    // epilogue: bias add + guarded store (c0,c1 at row; c2,c3 at row+8)
    bool is_half = (which == 1) || (which == 2);
    float*  Yf = (which == 0) ? g_q : g_s;
    __half* Yh = (which == 1) ? g_kh : g_vh;

#pragma unroll
    for (int i = 0; i < 2; i++) {
        int rg = row0 + wm * 32 + i * 16 + ly;
#pragma unroll
        for (int j = 0; j < 8; j++) {
            int cg = wn * 64 + j * 8 + 2 * lx;
            float2 bb = *(const float2*)(bias + cg);
            float o00 = acc[i][j][0] + bb.x, o01 = acc[i][j][1] + bb.y;
            float o10 = acc[i][j][2] + bb.x, o11 = acc[i][j][3] + bb.y;
            if (is_half) {
                if (rg < N)
                    *(__half2*)(Yh + (size_t)rg * 128 + cg) = __floats2half2_rn(o00, o01);
                if (rg + 8 < N)
                    *(__half2*)(Yh + (size_t)(rg + 8) * 128 + cg) = __floats2half2_rn(o10, o11);
            } else {
                if (rg < N)
                    *(float2*)(Yf + (size_t)rg * 128 + cg) = make_float2(o00, o01);
                if (rg + 8 < N)
                    *(float2*)(Yf + (size_t)(rg + 8) * 128 + cg) = make_float2(o10, o11);
            }
        }
    }
}

// ---------------- fused attention: gather + online softmax + skip ----------
// TWO nodes per warp: each 16-lane half handles one node, 8 channels per lane.
// One shfl_xor(1) completes each 16-ch head dot. k/v fp16, math fp32.
__device__ __forceinline__ float dot8(float4 q0, float4 q1, uint4 u)
{
    float2 f0 = __half22float2(*reinterpret_cast<__half2*>(&u.x));
    float2 f1 = __half22float2(*reinterpret_cast<__half2*>(&u.y));
    float2 f2 = __half22float2(*reinterpret_cast<__half2*>(&u.z));
    float2 f3 = __half22float2(*reinterpret_cast<__half2*>(&u.w));
    return q0.x * f0.x + q0.y * f0.y + q0.z * f1.x + q0.w * f1.y
         + q1.x * f2.x + q1.y * f2.y + q1.z * f3.x + q1.w * f3.y;
}

__device__ __forceinline__ void acc8(float4& a0, float4& a1, float w, uint4 u)
{
    float2 f0 = __half22float2(*reinterpret_cast<__half2*>(&u.x));
    float2 f1 = __half22float2(*reinterpret_cast<__half2*>(&u.y));
    float2 f2 = __half22float2(*reinterpret_cast<__half2*>(&u.z));
    float2 f3 = __half22float2(*reinterpret_cast<__half2*>(&u.w));
    a0.x += w * f0.x; a0.y += w * f0.y; a0.z += w * f1.x; a0.w += w * f1.y;
    a1.x += w * f2.x; a1.y += w * f2.y; a1.z += w * f3.x; a1.w += w * f3.y;
}

__global__ void attn_gather_kernel(float* __restrict__ outp, int N, int do_relu)
{
    int warp_id = blockIdx.x * 8 + (threadIdx.x >> 5);
    int lane = threadIdx.x & 31;
    int half = lane >> 4;                 // 0 or 1: which node in this warp
    int hl   = lane & 15;                 // lane within half; channels [8hl, 8hl+8)
    int node = warp_id * 2 + half;
    if (node >= N) return;
    unsigned mask = 0xFFFFu << (half * 16);

    size_t off = (size_t)node * D;
    float4 q0 = *((const float4*)(g_q + off) + 2 * hl);
    float4 q1 = *((const float4*)(g_q + off) + 2 * hl + 1);

    int beg = g_rowptr[node];
    int end = g_rowptr[node + 1];

    float m = NEG_INF;
    float den = 0.f;
    float4 acc0 = make_float4(0.f, 0.f, 0.f, 0.f);
    float4 acc1 = make_float4(0.f, 0.f, 0.f, 0.f);

    int i = beg;
    for (; i + 4 <= end; i += 4) {
        int s0 = __ldg(&g_csrc[i]);
        int s1 = __ldg(&g_csrc[i + 1]);
        int s2 = __ldg(&g_csrc[i + 2]);
        int s3 = __ldg(&g_csrc[i + 3]);
        uint4 k0 = __ldg((const uint4*)(g_kh + (size_t)s0 * D) + hl);
        uint4 k1 = __ldg((const uint4*)(g_kh + (size_t)s1 * D) + hl);
        uint4 k2 = __ldg((const uint4*)(g_kh + (size_t)s2 * D) + hl);
        uint4 k3 = __ldg((const uint4*)(g_kh + (size_t)s3 * D) + hl);
        uint4 v0 = __ldg((const uint4*)(g_vh + (size_t)s0 * D) + hl);
        uint4 v1 = __ldg((const uint4*)(g_vh + (size_t)s1 * D) + hl);
        uint4 v2 = __ldg((const uint4*)(g_vh + (size_t)s2 * D) + hl);
        uint4 v3 = __ldg((const uint4*)(g_vh + (size_t)s3 * D) + hl);

        float a0 = dot8(q0, q1, k0);
        float a1 = dot8(q0, q1, k1);
        float a2 = dot8(q0, q1, k2);
        float a3 = dot8(q0, q1, k3);
        a0 = (a0 + __shfl_xor_sync(mask, a0, 1)) * ATT_SCALE;
        a1 = (a1 + __shfl_xor_sync(mask, a1, 1)) * ATT_SCALE;
        a2 = (a2 + __shfl_xor_sync(mask, a2, 1)) * ATT_SCALE;
        a3 = (a3 + __shfl_xor_sync(mask, a3, 1)) * ATT_SCALE;

        float mx = fmaxf(fmaxf(a0, a1), fmaxf(a2, a3));
        float newm = fmaxf(m, mx);
        float c  = __expf(m - newm);      // first group: exp(-inf)=0
        float w0 = __expf(a0 - newm);
        float w1 = __expf(a1 - newm);
        float w2 = __expf(a2 - newm);
        float w3 = __expf(a3 - newm);
        den = den * c + (w0 + w1) + (w2 + w3);
        acc0.x *= c; acc0.y *= c; acc0.z *= c; acc0.w *= c;
        acc1.x *= c; acc1.y *= c; acc1.z *= c; acc1.w *= c;
        acc8(acc0, acc1, w0, v0);
        acc8(acc0, acc1, w1, v1);
        acc8(acc0, acc1, w2, v2);
        acc8(acc0, acc1, w3, v3);
        m = newm;
    }
    for (; i < end; i++) {
        int s = __ldg(&g_csrc[i]);
        uint4 kv = __ldg((const uint4*)(g_kh + (size_t)s * D) + hl);
        uint4 vv = __ldg((const uint4*)(g_vh + (size_t)s * D) + hl);
        float a = dot8(q0, q1, kv);
        a = (a + __shfl_xor_sync(mask, a, 1)) * ATT_SCALE;
        float newm = fmaxf(m, a);
        float c = __expf(m - newm);
        float w = __expf(a - newm);
        den = den * c + w;
        acc0.x *= c; acc0.y *= c; acc0.z *= c; acc0.w *= c;
        acc1.x *= c; acc1.y *= c; acc1.z *= c; acc1.w *= c;
        acc8(acc0, acc1, w, vv);
        m = newm;
    }

    float4 sv0 = *((const float4*)(g_s + off) + 2 * hl);
    float4 sv1 = *((const float4*)(g_s + off) + 2 * hl + 1);
    float inv = (den > 0.f) ? 1.f / den : 0.f;
    float4 o0 = make_float4(sv0.x + acc0.x * inv, sv0.y + acc0.y * inv,
                            sv0.z + acc0.z * inv, sv0.w + acc0.w * inv);
    float4 o1 = make_float4(sv1.x + acc1.x * inv, sv1.y + acc1.y * inv,
                            sv1.z + acc1.z * inv, sv1.w + acc1.w * inv);
    if (do_relu) {
        o0.x = fmaxf(o0.x, 0.f); o0.y = fmaxf(o0.y, 0.f);
        o0.z = fmaxf(o0.z, 0.f); o0.w = fmaxf(o0.w, 0.f);
        o1.x = fmaxf(o1.x, 0.f); o1.y = fmaxf(o1.y, 0.f);
        o1.z = fmaxf(o1.z, 0.f); o1.w = fmaxf(o1.w, 0.f);
    }
    float* op = outp ? outp : g_h;
    *((float4*)(op + off) + 2 * hl) = o0;
    *((float4*)(op + off) + 2 * hl + 1) = o1;
}

// ---------------- host ------------------------------------------------------
extern "C" void kernel_launch(void* const* d_in, const int* in_sizes, int n_in,
                              void* d_out, int out_size)
{
    const float* x = (const float*)d_in[0];
    const int* ei32 = (const int*)d_in[1];
    int N = in_sizes[0] / 128;
    int E = in_sizes[1] / 2;

    const float* W[2][4] = {
        {(const float*)d_in[3], (const float*)d_in[5], (const float*)d_in[7], (const float*)d_in[9]},
        {(const float*)d_in[11], (const float*)d_in[13], (const float*)d_in[15], (const float*)d_in[17]}
    };
    const float* B[2][4] = {
        {(const float*)d_in[4], (const float*)d_in[6], (const float*)d_in[8], (const float*)d_in[10]},
        {(const float*)d_in[12], (const float*)d_in[14], (const float*)d_in[16], (const float*)d_in[18]}
    };

    // one-time side stream + fork/join events (resources only; work is
    // identical on every call)
    static cudaStream_t s2 = nullptr;
    static cudaEvent_t evFork = nullptr, evJoin = nullptr;
    if (!s2) {
        cudaStreamCreateWithFlags(&s2, cudaStreamNonBlocking);
        cudaEventCreateWithFlags(&evFork, cudaEventDisableTiming);
        cudaEventCreateWithFlags(&evJoin, cudaEventDisableTiming);
    }

    int Ntot = N + 1;
    int nscan = (Ntot + 1023) / 1024;

    // fork: CSR build on s2, overlapped with layer-0 GEMM on the main stream
    cudaEventRecord(evFork, 0);
    cudaStreamWaitEvent(s2, evFork, 0);
    detect_kernel<<<1, 256, 0, s2>>>(ei32);
    zero_cnt_kernel<<<(Ntot + 255) / 256, 256, 0, s2>>>(N);
    convert_hist_kernel<<<(E + 255) / 256, 256, 0, s2>>>(ei32, E);
    scan1_kernel<<<nscan, 1024, 0, s2>>>(Ntot);
    scan2_kernel<<<1, 32, 0, s2>>>(nscan);
    scan3_kernel<<<nscan, 1024, 0, s2>>>(Ntot);
    scatter_kernel<<<(E + 255) / 256, 256, 0, s2>>>(E);
    cudaEventRecord(evJoin, s2);

    dim3 ggrid(4, (N + 127) / 128);
    int attn_blocks = (N + 15) / 16;   // 2 nodes per warp, 8 warps per block

    // layer 0
    gemm4_kernel<<<ggrid, 256>>>(x,
        W[0][0], W[0][1], W[0][2], W[0][3],
        B[0][0], B[0][1], B[0][2], B[0][3], N);
    cudaStreamWaitEvent(0, evJoin, 0);   // join: attention needs CSR
    attn_gather_kernel<<<attn_blocks, 256>>>(nullptr, N, 1);

    // layer 1
    gemm4_kernel<<<ggrid, 256>>>(nullptr,
        W[1][0], W[1][1], W[1][2], W[1][3],
        B[1][0], B[1][1], B[1][2], B[1][3], N);
    attn_gather_kernel<<<attn_blocks, 256>>>((float*)d_out, N, 0);
}